// round 1
// baseline (speedup 1.0000x reference)
#include <cuda_runtime.h>
#include <cstdint>

// Problem constants
#define TOK   2048
#define HID   2880
#define INTER 2880
#define NEXP  8
#define TOPK  4
#define N1    (2*INTER)        // 5760
#define MAXR  (NEXP*TOK)       // 16384

__device__ __constant__ float c_alpha = 1.702f;
__device__ __constant__ float c_limit = 7.0f;

// ---------------- static scratch (no cudaMalloc allowed) ----------------
__device__ int   g_cnt[NEXP];
__device__ int   g_tok[NEXP][TOK];        // gathered token ids per expert
__device__ int   g_pos[TOK][TOPK];        // token -> (expert*TOK + slot)
__device__ float g_w  [TOK][TOPK];        // token -> combine weight
__device__ float g_h  [94371840];         // MAXR * N1   (377 MB)
__device__ float g_act[47185920];         // MAXR * INTER (189 MB)
__device__ float g_yp [47185920];         // MAXR * HID   (189 MB)

// ---------------- packed fp32x2 helpers (Blackwell FFMA2) ----------------
__device__ __forceinline__ unsigned long long bcast2(float v) {
    unsigned long long r;
    asm("mov.b64 %0, {%1, %1};" : "=l"(r) : "f"(v));
    return r;
}
__device__ __forceinline__ void ffma2(unsigned long long& d,
                                      unsigned long long a,
                                      unsigned long long b) {
    asm("fma.rn.f32x2 %0, %1, %2, %0;" : "+l"(d) : "l"(a), "l"(b));
}
__device__ __forceinline__ float2 unpack2(unsigned long long v) {
    float2 r;
    asm("mov.b64 {%0, %1}, %2;" : "=f"(r.x), "=f"(r.y) : "l"(v));
    return r;
}

// ---------------- init ----------------
__global__ void init_kernel() {
    if (threadIdx.x < NEXP) g_cnt[threadIdx.x] = 0;
}

// ---------------- router: logits, top-4, softmax, compaction ----------------
__global__ void router_kernel(const float* __restrict__ x,
                              const float* __restrict__ gw,
                              const float* __restrict__ gb) {
    int warp = threadIdx.x >> 5;
    int lane = threadIdx.x & 31;
    int t = blockIdx.x * 8 + warp;
    if (t >= TOK) return;
    const float* xr = x + (size_t)t * HID;

    float acc[NEXP];
#pragma unroll
    for (int e = 0; e < NEXP; e++) acc[e] = 0.f;

    for (int h = lane; h < HID; h += 32) {
        float xv = xr[h];
        const float4* g4 = reinterpret_cast<const float4*>(gw + (size_t)h * NEXP);
        float4 ga = g4[0];
        float4 gbv = g4[1];
        acc[0] += xv * ga.x;  acc[1] += xv * ga.y;
        acc[2] += xv * ga.z;  acc[3] += xv * ga.w;
        acc[4] += xv * gbv.x; acc[5] += xv * gbv.y;
        acc[6] += xv * gbv.z; acc[7] += xv * gbv.w;
    }
#pragma unroll
    for (int e = 0; e < NEXP; e++) {
#pragma unroll
        for (int off = 16; off; off >>= 1)
            acc[e] += __shfl_xor_sync(0xffffffffu, acc[e], off);
    }
    if (lane == 0) {
        float lg[NEXP];
#pragma unroll
        for (int e = 0; e < NEXP; e++) lg[e] = acc[e] + gb[e];
        int   idx[TOPK];
        float val[TOPK];
        unsigned mask = 0;
#pragma unroll
        for (int k = 0; k < TOPK; k++) {
            float best = -3.4e38f; int bi = 0;
#pragma unroll
            for (int e = 0; e < NEXP; e++)
                if (!((mask >> e) & 1u) && lg[e] > best) { best = lg[e]; bi = e; }
            mask |= 1u << bi;
            idx[k] = bi; val[k] = best;
        }
        float m = val[0], s = 0.f, w[TOPK];
#pragma unroll
        for (int k = 0; k < TOPK; k++) { w[k] = expf(val[k] - m); s += w[k]; }
        float inv = 1.f / s;
#pragma unroll
        for (int k = 0; k < TOPK; k++) {
            int e = idx[k];
            int p = atomicAdd(&g_cnt[e], 1);
            g_tok[e][p]  = t;
            g_pos[t][k]  = e * TOK + p;
            g_w[t][k]    = w[k] * inv;
        }
    }
}

// ---------------- tiled SGEMM with f32x2 FMAs ----------------
// FIRST=true : A = x (gathered rows via g_tok), B = w1, C = g_h, N = N1
// FIRST=false: A = g_act (direct rows),        B = w2, C = g_yp, N = HID
template<bool FIRST, int N>
__global__ __launch_bounds__(256, 2)
void gemm_kernel(const float* __restrict__ X,
                 const float* __restrict__ B,
                 const float* __restrict__ bias) {
    constexpr int K = HID;  // 2880
    int e  = blockIdx.z;
    int ne = g_cnt[e];
    int m0 = blockIdx.y * 128;
    if (m0 >= ne) return;
    int n0 = blockIdx.x * 128;

    __shared__ float As[16][128];
    __shared__ float Bs[16][128];

    int tid = threadIdx.x;
    int tx = tid & 15;       // output col group (8 cols)
    int ty = tid >> 4;       // output row group (8 rows)

    // --- A load slot: row lm, k-quad lkq (8 consecutive k) ---
    int lm  = tid >> 1;          // 0..127
    int lkq = (tid & 1) * 8;     // 0 or 8
    const float* Arow;
    if (FIRST) {
        int mi = m0 + lm;
        if (mi >= ne) mi = ne - 1;         // deterministic clamp
        int tokid = g_tok[e][mi];
        Arow = X + (size_t)tokid * K;
    } else {
        Arow = g_act + (size_t)(e * TOK + m0 + lm) * K;
    }

    const float* Be = B + (size_t)e * K * N;

    // --- B load slot: rows bk & bk+8, float4 at col bc ---
    int bk = tid >> 5;            // 0..7
    int bc = (tid & 31) * 4;      // 0..124
    bool bvalid = (N % 128 == 0) ? true : ((n0 + bc) < N);

    unsigned long long acc[8][4];
#pragma unroll
    for (int i = 0; i < 8; i++)
#pragma unroll
        for (int j = 0; j < 4; j++) acc[i][j] = 0ull;

    for (int k0 = 0; k0 < K; k0 += 16) {
        float4 a0 = *reinterpret_cast<const float4*>(Arow + k0 + lkq);
        float4 a1 = *reinterpret_cast<const float4*>(Arow + k0 + lkq + 4);
        float4 b0 = make_float4(0.f, 0.f, 0.f, 0.f), b1 = b0;
        if (bvalid) {
            b0 = *reinterpret_cast<const float4*>(Be + (size_t)(k0 + bk) * N + n0 + bc);
            b1 = *reinterpret_cast<const float4*>(Be + (size_t)(k0 + bk + 8) * N + n0 + bc);
        }
        __syncthreads();
        As[lkq + 0][lm] = a0.x; As[lkq + 1][lm] = a0.y;
        As[lkq + 2][lm] = a0.z; As[lkq + 3][lm] = a0.w;
        As[lkq + 4][lm] = a1.x; As[lkq + 5][lm] = a1.y;
        As[lkq + 6][lm] = a1.z; As[lkq + 7][lm] = a1.w;
        *reinterpret_cast<float4*>(&Bs[bk][bc])     = b0;
        *reinterpret_cast<float4*>(&Bs[bk + 8][bc]) = b1;
        __syncthreads();

#pragma unroll
        for (int k = 0; k < 16; k++) {
            float4 av0 = *reinterpret_cast<const float4*>(&As[k][ty * 8]);
            float4 av1 = *reinterpret_cast<const float4*>(&As[k][ty * 8 + 4]);
            const unsigned long long* brow =
                reinterpret_cast<const unsigned long long*>(&Bs[k][tx * 8]);
            unsigned long long bp0 = brow[0], bp1 = brow[1],
                               bp2 = brow[2], bp3 = brow[3];
            unsigned long long ap[8];
            ap[0] = bcast2(av0.x); ap[1] = bcast2(av0.y);
            ap[2] = bcast2(av0.z); ap[3] = bcast2(av0.w);
            ap[4] = bcast2(av1.x); ap[5] = bcast2(av1.y);
            ap[6] = bcast2(av1.z); ap[7] = bcast2(av1.w);
#pragma unroll
            for (int i = 0; i < 8; i++) {
                ffma2(acc[i][0], ap[i], bp0);
                ffma2(acc[i][1], ap[i], bp1);
                ffma2(acc[i][2], ap[i], bp2);
                ffma2(acc[i][3], ap[i], bp3);
            }
        }
    }

    float* Cbase = FIRST ? g_h : g_yp;
#pragma unroll
    for (int i = 0; i < 8; i++) {
        int mi = m0 + ty * 8 + i;
        if (mi >= ne) continue;
        float* Crow = Cbase + (size_t)(e * TOK + mi) * N + n0;
#pragma unroll
        for (int j = 0; j < 4; j++) {
            int n = tx * 8 + j * 2;
            if ((N % 128 != 0) && (n0 + n >= N)) continue;
            float2 v = unpack2(acc[i][j]);
            v.x += bias[(size_t)e * N + n0 + n];
            v.y += bias[(size_t)e * N + n0 + n + 1];
            *reinterpret_cast<float2*>(Crow + n) = v;
        }
    }
}

// ---------------- clamped SwiGLU ----------------
__device__ __forceinline__ float swi(float g, float l) {
    g = fminf(g, c_limit);
    l = fminf(fmaxf(l, -c_limit), c_limit);
    float s = 1.f / (1.f + expf(-c_alpha * g));
    return g * s * (l + 1.0f);
}

__global__ void swiglu_kernel() {
    int idx = blockIdx.x * blockDim.x + threadIdx.x;  // float4 index
    const int per_row = INTER / 4;                    // 720
    if (idx >= MAXR * per_row) return;
    int r  = idx / per_row;
    int c4 = idx - r * per_row;
    if ((r & (TOK - 1)) >= g_cnt[r / TOK]) return;    // skip unused rows
    size_t base = (size_t)r * N1 + (size_t)c4 * 4;
    float4 gv = *reinterpret_cast<const float4*>(&g_h[base]);
    float4 lv = *reinterpret_cast<const float4*>(&g_h[base + INTER]);
    float4 o;
    o.x = swi(gv.x, lv.x);
    o.y = swi(gv.y, lv.y);
    o.z = swi(gv.z, lv.z);
    o.w = swi(gv.w, lv.w);
    *reinterpret_cast<float4*>(&g_act[(size_t)r * INTER + (size_t)c4 * 4]) = o;
}

// ---------------- weighted combine (deterministic, no atomics) ----------------
__global__ void combine_kernel(float* __restrict__ y) {
    int idx = blockIdx.x * blockDim.x + threadIdx.x;  // float4 index
    const int per_row = HID / 4;                      // 720
    if (idx >= TOK * per_row) return;
    int t = idx / per_row;
    int c = (idx - t * per_row) * 4;
    float4 accv = make_float4(0.f, 0.f, 0.f, 0.f);
#pragma unroll
    for (int k = 0; k < TOPK; k++) {
        int   p = g_pos[t][k];
        float wv = g_w[t][k];
        float4 v = *reinterpret_cast<const float4*>(&g_yp[(size_t)p * HID + c]);
        accv.x += wv * v.x;
        accv.y += wv * v.y;
        accv.z += wv * v.z;
        accv.w += wv * v.w;
    }
    *reinterpret_cast<float4*>(&y[(size_t)t * HID + c]) = accv;
}

// ---------------- launch ----------------
extern "C" void kernel_launch(void* const* d_in, const int* in_sizes, int n_in,
                              void* d_out, int out_size) {
    const float* x  = (const float*)d_in[0];
    const float* gw = (const float*)d_in[1];
    const float* gb = (const float*)d_in[2];
    const float* w1 = (const float*)d_in[3];
    const float* b1 = (const float*)d_in[4];
    const float* w2 = (const float*)d_in[5];
    const float* b2 = (const float*)d_in[6];
    float* y = (float*)d_out;

    init_kernel<<<1, 32>>>();
    router_kernel<<<TOK / 8, 256>>>(x, gw, gb);

    // GEMM1: [ne,2880] x [2880,5760] -> g_h  (N1 = 5760 = 45*128 exact)
    gemm_kernel<true, N1><<<dim3(45, 16, NEXP), 256>>>(x, w1, b1);

    swiglu_kernel<<<(MAXR * (INTER / 4) + 255) / 256, 256>>>();

    // GEMM2: [ne,2880] x [2880,2880] -> g_yp (N = 2880, 23 col-blocks w/ guards)
    gemm_kernel<false, HID><<<dim3(23, 16, NEXP), 256>>>(nullptr, w2, b2);

    combine_kernel<<<(TOK * (HID / 4) + 255) / 256, 256>>>(y);
}

// round 5
// speedup vs baseline: 1.9455x; 1.9455x over previous
#include <cuda_runtime.h>
#include <cuda_bf16.h>
#include <cstdint>

#define TOK   2048
#define HID   2880
#define INTER 2880
#define NEXP  8
#define TOPK  4
#define N1    (2*INTER)        // 5760
#define MAXR  (NEXP*TOK)       // 16384
#define KDIM  2880

__device__ __constant__ float c_alpha = 1.702f;
__device__ __constant__ float c_limit = 7.0f;

// ---------------- static scratch ----------------
__device__ int   g_cnt[NEXP];
__device__ int   g_tok[NEXP][TOK];
__device__ int   g_pos[TOK][TOPK];
__device__ float g_w  [TOK][TOPK];
__device__ __align__(16) float g_h [(size_t)MAXR * N1];
__device__ __align__(16) float g_yp[(size_t)MAXR * HID];
__device__ __align__(16) __nv_bfloat16 g_xh [(size_t)TOK * KDIM];
__device__ __align__(16) __nv_bfloat16 g_xl [(size_t)TOK * KDIM];
__device__ __align__(16) __nv_bfloat16 g_w1h[(size_t)NEXP * N1 * KDIM];
__device__ __align__(16) __nv_bfloat16 g_w1l[(size_t)NEXP * N1 * KDIM];
__device__ __align__(16) __nv_bfloat16 g_w2h[(size_t)NEXP * HID * KDIM];
__device__ __align__(16) __nv_bfloat16 g_w2l[(size_t)NEXP * HID * KDIM];
__device__ __align__(16) __nv_bfloat16 g_ah [(size_t)MAXR * KDIM];
__device__ __align__(16) __nv_bfloat16 g_al [(size_t)MAXR * KDIM];

// ---------------- helpers ----------------
__device__ __forceinline__ uint32_t smem_to_u32(const void* p) {
    uint32_t a;
    asm("{ .reg .u64 t; cvta.to.shared.u64 t, %1; cvt.u32.u64 %0, t; }"
        : "=r"(a) : "l"(p));
    return a;
}
__device__ __forceinline__ void ldsm4(uint32_t* r, uint32_t addr) {
    asm volatile("ldmatrix.sync.aligned.m8n8.x4.shared.b16 {%0,%1,%2,%3}, [%4];"
                 : "=r"(r[0]), "=r"(r[1]), "=r"(r[2]), "=r"(r[3])
                 : "r"(addr) : "memory");
}
__device__ __forceinline__ void mma_bf16(float* c, const uint32_t* a, const uint32_t* b) {
    asm volatile(
        "mma.sync.aligned.m16n8k16.row.col.f32.bf16.bf16.f32 "
        "{%0,%1,%2,%3}, {%4,%5,%6,%7}, {%8,%9}, {%0,%1,%2,%3};"
        : "+f"(c[0]), "+f"(c[1]), "+f"(c[2]), "+f"(c[3])
        : "r"(a[0]), "r"(a[1]), "r"(a[2]), "r"(a[3]), "r"(b[0]), "r"(b[1]));
}
__device__ __forceinline__ void cpa16(uint32_t dst, const void* src) {
    asm volatile("cp.async.cg.shared.global [%0], [%1], 16;"
                 :: "r"(dst), "l"(src) : "memory");
}
#define CP_COMMIT() asm volatile("cp.async.commit_group;" ::: "memory")
#define CP_WAIT0()  asm volatile("cp.async.wait_group 0;" ::: "memory")

__device__ __forceinline__ void split2(float v, __nv_bfloat16& h, __nv_bfloat16& l) {
    h = __float2bfloat16(v);
    l = __float2bfloat16(v - __bfloat162float(h));
}
union B4 { unsigned long long u; __nv_bfloat16 b[4]; };

// ---------------- init ----------------
__global__ void init_kernel() {
    if (threadIdx.x < NEXP) g_cnt[threadIdx.x] = 0;
}

// ---------------- router ----------------
__global__ void router_kernel(const float* __restrict__ x,
                              const float* __restrict__ gw,
                              const float* __restrict__ gb) {
    int warp = threadIdx.x >> 5, lane = threadIdx.x & 31;
    int t = blockIdx.x * 8 + warp;
    if (t >= TOK) return;
    const float* xr = x + (size_t)t * HID;
    float acc[NEXP];
#pragma unroll
    for (int e = 0; e < NEXP; e++) acc[e] = 0.f;
    for (int h = lane; h < HID; h += 32) {
        float xv = xr[h];
        const float4* g4 = reinterpret_cast<const float4*>(gw + (size_t)h * NEXP);
        float4 ga = g4[0], gbv = g4[1];
        acc[0] += xv * ga.x;  acc[1] += xv * ga.y;
        acc[2] += xv * ga.z;  acc[3] += xv * ga.w;
        acc[4] += xv * gbv.x; acc[5] += xv * gbv.y;
        acc[6] += xv * gbv.z; acc[7] += xv * gbv.w;
    }
#pragma unroll
    for (int e = 0; e < NEXP; e++)
#pragma unroll
        for (int off = 16; off; off >>= 1)
            acc[e] += __shfl_xor_sync(0xffffffffu, acc[e], off);
    if (lane == 0) {
        float lg[NEXP];
#pragma unroll
        for (int e = 0; e < NEXP; e++) lg[e] = acc[e] + gb[e];
        int idx[TOPK]; float val[TOPK]; unsigned mask = 0;
#pragma unroll
        for (int k = 0; k < TOPK; k++) {
            float best = -3.4e38f; int bi = 0;
#pragma unroll
            for (int e = 0; e < NEXP; e++)
                if (!((mask >> e) & 1u) && lg[e] > best) { best = lg[e]; bi = e; }
            mask |= 1u << bi; idx[k] = bi; val[k] = best;
        }
        float m = val[0], s = 0.f, w[TOPK];
#pragma unroll
        for (int k = 0; k < TOPK; k++) { w[k] = expf(val[k] - m); s += w[k]; }
        float inv = 1.f / s;
#pragma unroll
        for (int k = 0; k < TOPK; k++) {
            int e = idx[k];
            int p = atomicAdd(&g_cnt[e], 1);
            g_tok[e][p] = t;
            g_pos[t][k] = e * TOK + p;
            g_w[t][k]   = w[k] * inv;
        }
    }
}

// ---------------- x -> bf16 hi/lo ----------------
__global__ void convert_x_kernel(const float* __restrict__ x) {
    size_t i4 = (size_t)blockIdx.x * blockDim.x + threadIdx.x;
    if (i4 >= (size_t)TOK * KDIM / 4) return;
    float4 v = reinterpret_cast<const float4*>(x)[i4];
    B4 h, l;
    split2(v.x, h.b[0], l.b[0]); split2(v.y, h.b[1], l.b[1]);
    split2(v.z, h.b[2], l.b[2]); split2(v.w, h.b[3], l.b[3]);
    reinterpret_cast<unsigned long long*>(g_xh)[i4] = h.u;
    reinterpret_cast<unsigned long long*>(g_xl)[i4] = l.u;
}

// ---------------- weight transpose + split (device-side symbol refs!) ------
// WHICH=0: w1 [e][k][N1] -> g_w1h/l [e][n][k];  WHICH=1: w2 -> g_w2h/l
template<int WHICH>
__global__ void transpose_split_kernel(const float* __restrict__ W) {
    constexpr int Kd = KDIM;
    constexpr int Nd = WHICH ? HID : N1;
    __nv_bfloat16* TH = WHICH ? g_w2h : g_w1h;   // device-code symbol ref
    __nv_bfloat16* TL = WHICH ? g_w2l : g_w1l;
    __shared__ float t[32][33];
    int e = blockIdx.z;
    int n0 = blockIdx.x * 32, k0 = blockIdx.y * 32;
    int tx = threadIdx.x & 7, ty = threadIdx.x >> 3;
    float4 v = *reinterpret_cast<const float4*>(
        W + ((size_t)e * Kd + k0 + ty) * Nd + n0 + tx * 4);
    t[ty][tx * 4 + 0] = v.x; t[ty][tx * 4 + 1] = v.y;
    t[ty][tx * 4 + 2] = v.z; t[ty][tx * 4 + 3] = v.w;
    __syncthreads();
    B4 h, l;
#pragma unroll
    for (int j = 0; j < 4; j++) split2(t[tx * 4 + j][ty], h.b[j], l.b[j]);
    size_t off = ((size_t)e * Nd + n0 + ty) * Kd + k0 + tx * 4;
    *reinterpret_cast<unsigned long long*>(TH + off) = h.u;
    *reinterpret_cast<unsigned long long*>(TL + off) = l.u;
}

// ---------------- mma.sync GEMM, canonical layout ----------------
// CTA tile 128(m) x 192(n); warps 2m x 4n, warp tile 64x48; K chunk 32 halves.
// SMEM: padded rows, stride 80B; A_hi/A_lo/B_hi/B_lo tiles; cp.async 2-stage.
#define KC      32
#define NCHUNK  (KDIM / KC)            // 90
#define SSTRIDE 80
#define OFF_AH  0
#define OFF_AL  10240
#define OFF_BH  20480
#define OFF_BL  35840
#define STAGE   51200
#define SMEM_GEMM (2 * STAGE + 512)    // 102912

template<bool FIRST, int NFULL>
__global__ __launch_bounds__(256, 1)
void mma_gemm_kernel(const float* __restrict__ bias) {
    extern __shared__ __align__(1024) char smem[];
    int tid = threadIdx.x;
    int e = blockIdx.z;
    int ne = g_cnt[e];
    int m0 = blockIdx.x * 128;
    if (m0 >= ne) return;
    int n0 = blockIdx.y * 192;

    const __nv_bfloat16* Ah_ = FIRST ? g_xh : g_ah;
    const __nv_bfloat16* Al_ = FIRST ? g_xl : g_al;
    const __nv_bfloat16* Bh_ = FIRST ? g_w1h : g_w2h;
    const __nv_bfloat16* Bl_ = FIRST ? g_w1l : g_w2l;
    float* C = FIRST ? g_h : g_yp;

    int* rowid = reinterpret_cast<int*>(smem + 2 * STAGE);
    if (tid < 128) {
        int mi = m0 + tid; if (mi >= ne) mi = ne - 1;
        rowid[tid] = FIRST ? g_tok[e][mi] : (e * TOK + mi);
    }
    __syncthreads();

    uint32_t sb = smem_to_u32(smem);
    int lrow = tid >> 2;               // 0..63
    int lseg = tid & 3;
    size_t ebase = (size_t)e * NFULL + n0;
    int ra0 = rowid[lrow], ra1 = rowid[lrow + 64];

    auto load_stage = [&](int stg, int chunk) {
        uint32_t sbase = sb + stg * STAGE;
        size_t k0 = (size_t)chunk * KC;
        const __nv_bfloat16* a;
        a = Ah_ + (size_t)ra0 * KDIM + k0 + lseg * 8;
        cpa16(sbase + OFF_AH + lrow * SSTRIDE + lseg * 16, a);
        a = Ah_ + (size_t)ra1 * KDIM + k0 + lseg * 8;
        cpa16(sbase + OFF_AH + (lrow + 64) * SSTRIDE + lseg * 16, a);
        a = Al_ + (size_t)ra0 * KDIM + k0 + lseg * 8;
        cpa16(sbase + OFF_AL + lrow * SSTRIDE + lseg * 16, a);
        a = Al_ + (size_t)ra1 * KDIM + k0 + lseg * 8;
        cpa16(sbase + OFF_AL + (lrow + 64) * SSTRIDE + lseg * 16, a);
#pragma unroll
        for (int jb = 0; jb < 3; jb++) {
            const __nv_bfloat16* bsrc =
                Bh_ + (ebase + lrow + jb * 64) * KDIM + k0 + lseg * 8;
            cpa16(sbase + OFF_BH + (lrow + jb * 64) * SSTRIDE + lseg * 16, bsrc);
        }
#pragma unroll
        for (int jb = 0; jb < 3; jb++) {
            const __nv_bfloat16* bsrc =
                Bl_ + (ebase + lrow + jb * 64) * KDIM + k0 + lseg * 8;
            cpa16(sbase + OFF_BL + (lrow + jb * 64) * SSTRIDE + lseg * 16, bsrc);
        }
    };

    int w = tid >> 5, lane = tid & 31;
    int wn = w & 3, wm = w >> 2;
    uint32_t row_add = (uint32_t)((lane & 7) + ((lane >> 3) & 1) * 8);
    uint32_t col16 = (uint32_t)(((lane >> 4) & 1) * 16);

    float c[4][6][4];
#pragma unroll
    for (int f = 0; f < 4; f++)
#pragma unroll
        for (int n = 0; n < 6; n++)
#pragma unroll
            for (int k = 0; k < 4; k++) c[f][n][k] = 0.f;

    load_stage(0, 0);
    CP_COMMIT();

    for (int i = 0; i < NCHUNK; i++) {
        CP_WAIT0();
        __syncthreads();
        if (i + 1 < NCHUNK) { load_stage((i + 1) & 1, i + 1); CP_COMMIT(); }

        uint32_t st = sb + (i & 1) * STAGE;
#pragma unroll
        for (int s = 0; s < 2; s++) {
            uint32_t sbyte = (uint32_t)(s * 32) + col16;
            uint32_t bh[6][2], bl[6][2];
#pragma unroll
            for (int np = 0; np < 3; np++) {
                uint32_t rb = (uint32_t)(wn * 48 + np * 16) + row_add;
                uint32_t t0[4], t1[4];
                ldsm4(t0, st + OFF_BH + rb * SSTRIDE + sbyte);
                ldsm4(t1, st + OFF_BL + rb * SSTRIDE + sbyte);
                bh[2 * np][0] = t0[0]; bh[2 * np][1] = t0[2];
                bh[2 * np + 1][0] = t0[1]; bh[2 * np + 1][1] = t0[3];
                bl[2 * np][0] = t1[0]; bl[2 * np][1] = t1[2];
                bl[2 * np + 1][0] = t1[1]; bl[2 * np + 1][1] = t1[3];
            }
#pragma unroll
            for (int f = 0; f < 4; f++) {
                uint32_t ra = (uint32_t)(wm * 64 + f * 16) + row_add;
                uint32_t ah[4], al[4];
                ldsm4(ah, st + OFF_AH + ra * SSTRIDE + sbyte);
                ldsm4(al, st + OFF_AL + ra * SSTRIDE + sbyte);
#pragma unroll
                for (int n = 0; n < 6; n++) {
                    mma_bf16(c[f][n], ah, bh[n]);
                    mma_bf16(c[f][n], al, bh[n]);
                    mma_bf16(c[f][n], ah, bl[n]);
                }
            }
        }
        __syncthreads();
    }

    int rbase = m0 + wm * 64 + (lane >> 2);
    int cbase = n0 + wn * 48 + (lane & 3) * 2;
    const float* be = bias + (size_t)e * NFULL;
#pragma unroll
    for (int f = 0; f < 4; f++) {
        int r0 = rbase + f * 16;
#pragma unroll
        for (int n = 0; n < 6; n++) {
            int gc = cbase + n * 8;
            float bx = be[gc], by = be[gc + 1];
            if (r0 < ne) {
                float2 v = make_float2(c[f][n][0] + bx, c[f][n][1] + by);
                *reinterpret_cast<float2*>(
                    C + (size_t)(e * TOK + r0) * NFULL + gc) = v;
            }
            if (r0 + 8 < ne) {
                float2 v = make_float2(c[f][n][2] + bx, c[f][n][3] + by);
                *reinterpret_cast<float2*>(
                    C + (size_t)(e * TOK + r0 + 8) * NFULL + gc) = v;
            }
        }
    }
}

// ---------------- clamped SwiGLU -> bf16 hi/lo ----------------
__device__ __forceinline__ float swi(float g, float l) {
    g = fminf(g, c_limit);
    l = fminf(fmaxf(l, -c_limit), c_limit);
    float s = 1.f / (1.f + expf(-c_alpha * g));
    return g * s * (l + 1.0f);
}
__global__ void swiglu_kernel() {
    int idx = blockIdx.x * blockDim.x + threadIdx.x;
    const int per_row = INTER / 4;
    if (idx >= MAXR * per_row) return;
    int r = idx / per_row;
    int c4 = idx - r * per_row;
    if ((r & (TOK - 1)) >= g_cnt[r / TOK]) return;
    size_t base = (size_t)r * N1 + (size_t)c4 * 4;
    float4 gv = *reinterpret_cast<const float4*>(&g_h[base]);
    float4 lv = *reinterpret_cast<const float4*>(&g_h[base + INTER]);
    float4 o;
    o.x = swi(gv.x, lv.x); o.y = swi(gv.y, lv.y);
    o.z = swi(gv.z, lv.z); o.w = swi(gv.w, lv.w);
    B4 h, l;
    split2(o.x, h.b[0], l.b[0]); split2(o.y, h.b[1], l.b[1]);
    split2(o.z, h.b[2], l.b[2]); split2(o.w, h.b[3], l.b[3]);
    size_t o8 = (size_t)r * (KDIM / 4) + c4;
    reinterpret_cast<unsigned long long*>(g_ah)[o8] = h.u;
    reinterpret_cast<unsigned long long*>(g_al)[o8] = l.u;
}

// ---------------- weighted combine ----------------
__global__ void combine_kernel(float* __restrict__ y) {
    int idx = blockIdx.x * blockDim.x + threadIdx.x;
    const int per_row = HID / 4;
    if (idx >= TOK * per_row) return;
    int t = idx / per_row;
    int c = (idx - t * per_row) * 4;
    float4 accv = make_float4(0.f, 0.f, 0.f, 0.f);
#pragma unroll
    for (int k = 0; k < TOPK; k++) {
        int p = g_pos[t][k];
        float wv = g_w[t][k];
        float4 v = *reinterpret_cast<const float4*>(&g_yp[(size_t)p * HID + c]);
        accv.x += wv * v.x; accv.y += wv * v.y;
        accv.z += wv * v.z; accv.w += wv * v.w;
    }
    *reinterpret_cast<float4*>(&y[(size_t)t * HID + c]) = accv;
}

// ---------------- launch ----------------
extern "C" void kernel_launch(void* const* d_in, const int* in_sizes, int n_in,
                              void* d_out, int out_size) {
    const float* x  = (const float*)d_in[0];
    const float* gw = (const float*)d_in[1];
    const float* gb = (const float*)d_in[2];
    const float* w1 = (const float*)d_in[3];
    const float* b1 = (const float*)d_in[4];
    const float* w2 = (const float*)d_in[5];
    const float* b2 = (const float*)d_in[6];
    float* y = (float*)d_out;

    cudaFuncSetAttribute(mma_gemm_kernel<true, N1>,
                         cudaFuncAttributeMaxDynamicSharedMemorySize, SMEM_GEMM);
    cudaFuncSetAttribute(mma_gemm_kernel<false, HID>,
                         cudaFuncAttributeMaxDynamicSharedMemorySize, SMEM_GEMM);

    init_kernel<<<1, 32>>>();
    router_kernel<<<TOK / 8, 256>>>(x, gw, gb);
    convert_x_kernel<<<(TOK * KDIM / 4 + 255) / 256, 256>>>(x);
    transpose_split_kernel<0><<<dim3(N1 / 32, KDIM / 32, NEXP), 256>>>(w1);
    transpose_split_kernel<1><<<dim3(HID / 32, KDIM / 32, NEXP), 256>>>(w2);

    mma_gemm_kernel<true, N1><<<dim3(16, 30, NEXP), 256, SMEM_GEMM>>>(b1);
    swiglu_kernel<<<(MAXR * (INTER / 4) + 255) / 256, 256>>>();
    mma_gemm_kernel<false, HID><<<dim3(16, 15, NEXP), 256, SMEM_GEMM>>>(b2);
    combine_kernel<<<(TOK * (HID / 4) + 255) / 256, 256>>>(y);
}

// round 6
// speedup vs baseline: 3.1618x; 1.6252x over previous
#include <cuda_runtime.h>
#include <cuda_fp16.h>
#include <cstdint>

#define TOK   2048
#define HID   2880
#define INTER 2880
#define NEXP  8
#define TOPK  4
#define N1    (2*INTER)        // 5760
#define MAXR  (NEXP*TOK)       // 16384
#define KDIM  2880

__device__ __constant__ float c_alpha = 1.702f;
__device__ __constant__ float c_limit = 7.0f;

// ---------------- static scratch ----------------
__device__ int   g_cnt[NEXP];
__device__ int   g_tok[NEXP][TOK];
__device__ int   g_pos[TOK][TOPK];
__device__ float g_w  [TOK][TOPK];
__device__ __align__(16) float g_h [(size_t)MAXR * N1];
__device__ __align__(16) float g_yp[(size_t)MAXR * HID];
__device__ __align__(16) __half g_xh [(size_t)TOK * KDIM];
__device__ __align__(16) __half g_xl [(size_t)TOK * KDIM];
__device__ __align__(16) __half g_w1h[(size_t)NEXP * N1 * KDIM];
__device__ __align__(16) __half g_w2h[(size_t)NEXP * HID * KDIM];
__device__ __align__(16) __half g_ah [(size_t)MAXR * KDIM];
__device__ __align__(16) __half g_al [(size_t)MAXR * KDIM];

// ---------------- helpers ----------------
__device__ __forceinline__ uint32_t smem_to_u32(const void* p) {
    uint32_t a;
    asm("{ .reg .u64 t; cvta.to.shared.u64 t, %1; cvt.u32.u64 %0, t; }"
        : "=r"(a) : "l"(p));
    return a;
}
__device__ __forceinline__ void ldsm4(uint32_t* r, uint32_t addr) {
    asm volatile("ldmatrix.sync.aligned.m8n8.x4.shared.b16 {%0,%1,%2,%3}, [%4];"
                 : "=r"(r[0]), "=r"(r[1]), "=r"(r[2]), "=r"(r[3])
                 : "r"(addr) : "memory");
}
__device__ __forceinline__ void mma_f16(float* c, const uint32_t* a, const uint32_t* b) {
    asm volatile(
        "mma.sync.aligned.m16n8k16.row.col.f32.f16.f16.f32 "
        "{%0,%1,%2,%3}, {%4,%5,%6,%7}, {%8,%9}, {%0,%1,%2,%3};"
        : "+f"(c[0]), "+f"(c[1]), "+f"(c[2]), "+f"(c[3])
        : "r"(a[0]), "r"(a[1]), "r"(a[2]), "r"(a[3]), "r"(b[0]), "r"(b[1]));
}
__device__ __forceinline__ void cpa16(uint32_t dst, const void* src) {
    asm volatile("cp.async.cg.shared.global [%0], [%1], 16;"
                 :: "r"(dst), "l"(src) : "memory");
}
#define CP_COMMIT() asm volatile("cp.async.commit_group;" ::: "memory")
#define CP_WAIT0()  asm volatile("cp.async.wait_group 0;" ::: "memory")

__device__ __forceinline__ void split2h(float v, __half& h, __half& l) {
    h = __float2half_rn(v);
    l = __float2half_rn(v - __half2float(h));
}
union H4 { unsigned long long u; __half h[4]; };

// ---------------- init ----------------
__global__ void init_kernel() {
    if (threadIdx.x < NEXP) g_cnt[threadIdx.x] = 0;
}

// ---------------- router ----------------
__global__ void router_kernel(const float* __restrict__ x,
                              const float* __restrict__ gw,
                              const float* __restrict__ gb) {
    int warp = threadIdx.x >> 5, lane = threadIdx.x & 31;
    int t = blockIdx.x * 8 + warp;
    if (t >= TOK) return;
    const float* xr = x + (size_t)t * HID;
    float acc[NEXP];
#pragma unroll
    for (int e = 0; e < NEXP; e++) acc[e] = 0.f;
    for (int h = lane; h < HID; h += 32) {
        float xv = xr[h];
        const float4* g4 = reinterpret_cast<const float4*>(gw + (size_t)h * NEXP);
        float4 ga = g4[0], gbv = g4[1];
        acc[0] += xv * ga.x;  acc[1] += xv * ga.y;
        acc[2] += xv * ga.z;  acc[3] += xv * ga.w;
        acc[4] += xv * gbv.x; acc[5] += xv * gbv.y;
        acc[6] += xv * gbv.z; acc[7] += xv * gbv.w;
    }
#pragma unroll
    for (int e = 0; e < NEXP; e++)
#pragma unroll
        for (int off = 16; off; off >>= 1)
            acc[e] += __shfl_xor_sync(0xffffffffu, acc[e], off);
    if (lane == 0) {
        float lg[NEXP];
#pragma unroll
        for (int e = 0; e < NEXP; e++) lg[e] = acc[e] + gb[e];
        int idx[TOPK]; float val[TOPK]; unsigned mask = 0;
#pragma unroll
        for (int k = 0; k < TOPK; k++) {
            float best = -3.4e38f; int bi = 0;
#pragma unroll
            for (int e = 0; e < NEXP; e++)
                if (!((mask >> e) & 1u) && lg[e] > best) { best = lg[e]; bi = e; }
            mask |= 1u << bi; idx[k] = bi; val[k] = best;
        }
        float m = val[0], s = 0.f, w[TOPK];
#pragma unroll
        for (int k = 0; k < TOPK; k++) { w[k] = expf(val[k] - m); s += w[k]; }
        float inv = 1.f / s;
#pragma unroll
        for (int k = 0; k < TOPK; k++) {
            int e = idx[k];
            int p = atomicAdd(&g_cnt[e], 1);
            g_tok[e][p] = t;
            g_pos[t][k] = e * TOK + p;
            g_w[t][k]   = w[k] * inv;
        }
    }
}

// ---------------- x -> fp16 hi/lo ----------------
__global__ void convert_x_kernel(const float* __restrict__ x) {
    size_t i4 = (size_t)blockIdx.x * blockDim.x + threadIdx.x;
    if (i4 >= (size_t)TOK * KDIM / 4) return;
    float4 v = reinterpret_cast<const float4*>(x)[i4];
    H4 h, l;
    split2h(v.x, h.h[0], l.h[0]); split2h(v.y, h.h[1], l.h[1]);
    split2h(v.z, h.h[2], l.h[2]); split2h(v.w, h.h[3], l.h[3]);
    reinterpret_cast<unsigned long long*>(g_xh)[i4] = h.u;
    reinterpret_cast<unsigned long long*>(g_xl)[i4] = l.u;
}

// ---------------- weight transpose + fp16 (hi only) ----------------
// WHICH=0: w1 [e][k][N1] -> g_w1h [e][n][k];  WHICH=1: w2 -> g_w2h
template<int WHICH>
__global__ void transpose_split_kernel(const float* __restrict__ W) {
    constexpr int Kd = KDIM;
    constexpr int Nd = WHICH ? HID : N1;
    __half* TH = WHICH ? g_w2h : g_w1h;       // device-code symbol ref
    __shared__ float t[32][33];
    int e = blockIdx.z;
    int n0 = blockIdx.x * 32, k0 = blockIdx.y * 32;
    int tx = threadIdx.x & 7, ty = threadIdx.x >> 3;
    float4 v = *reinterpret_cast<const float4*>(
        W + ((size_t)e * Kd + k0 + ty) * Nd + n0 + tx * 4);
    t[ty][tx * 4 + 0] = v.x; t[ty][tx * 4 + 1] = v.y;
    t[ty][tx * 4 + 2] = v.z; t[ty][tx * 4 + 3] = v.w;
    __syncthreads();
    H4 h;
#pragma unroll
    for (int j = 0; j < 4; j++) h.h[j] = __float2half_rn(t[tx * 4 + j][ty]);
    size_t off = ((size_t)e * Nd + n0 + ty) * Kd + k0 + tx * 4;
    *reinterpret_cast<unsigned long long*>(TH + off) = h.u;
}

// ---------------- mma.sync GEMM (fp16, 2-term A-split) ----------------
// CTA tile 128(m) x 192(n); warps 2m x 4n, warp tile 64x48; K chunk 64 halves.
// SMEM: padded rows (stride 144B, conflict-free); A_hi/A_lo/B_hi; 2 stages.
#define KC      64
#define NCHUNK  (KDIM / KC)            // 45
#define SSTRIDE 144
#define OFF_AH  0
#define OFF_AL  18432
#define OFF_BH  36864
#define STAGE   64512
#define SMEM_GEMM (2 * STAGE + 512)    // 129536

template<bool FIRST, int NFULL>
__global__ __launch_bounds__(256, 1)
void mma_gemm_kernel(const float* __restrict__ bias) {
    extern __shared__ __align__(1024) char smem[];
    int tid = threadIdx.x;
    int e = blockIdx.z;
    int ne = g_cnt[e];
    int m0 = blockIdx.x * 128;
    if (m0 >= ne) return;
    int n0 = blockIdx.y * 192;

    const __half* Ah_ = FIRST ? g_xh : g_ah;
    const __half* Al_ = FIRST ? g_xl : g_al;
    const __half* Bh_ = FIRST ? g_w1h : g_w2h;
    float* C = FIRST ? g_h : g_yp;

    int* rowid = reinterpret_cast<int*>(smem + 2 * STAGE);
    if (tid < 128) {
        int mi = m0 + tid; if (mi >= ne) mi = ne - 1;
        rowid[tid] = FIRST ? g_tok[e][mi] : (e * TOK + mi);
    }
    __syncthreads();

    uint32_t sb = smem_to_u32(smem);
    int r8  = tid >> 3;                // 0..31
    int seg = tid & 7;                 // 16B segment within 128B row
    size_t ebase = (size_t)e * NFULL + n0;
    int ra[4];
#pragma unroll
    for (int j = 0; j < 4; j++) ra[j] = rowid[r8 + 32 * j];

    auto load_stage = [&](int stg, int chunk) {
        uint32_t sbase = sb + stg * STAGE;
        size_t k0 = (size_t)chunk * KC + seg * 8;
#pragma unroll
        for (int j = 0; j < 4; j++) {
            uint32_t so = (uint32_t)(r8 + 32 * j) * SSTRIDE + seg * 16;
            cpa16(sbase + OFF_AH + so, Ah_ + (size_t)ra[j] * KDIM + k0);
            cpa16(sbase + OFF_AL + so, Al_ + (size_t)ra[j] * KDIM + k0);
        }
#pragma unroll
        for (int j = 0; j < 6; j++) {
            uint32_t so = (uint32_t)(r8 + 32 * j) * SSTRIDE + seg * 16;
            cpa16(sbase + OFF_BH + so,
                  Bh_ + (ebase + r8 + 32 * j) * KDIM + k0);
        }
    };

    int w = tid >> 5, lane = tid & 31;
    int wn = w & 3, wm = w >> 2;
    uint32_t row_add = (uint32_t)((lane & 7) + ((lane >> 3) & 1) * 8);
    uint32_t col16 = (uint32_t)(((lane >> 4) & 1) * 16);

    float c[4][6][4];
#pragma unroll
    for (int f = 0; f < 4; f++)
#pragma unroll
        for (int n = 0; n < 6; n++)
#pragma unroll
            for (int k = 0; k < 4; k++) c[f][n][k] = 0.f;

    load_stage(0, 0);
    CP_COMMIT();

    for (int i = 0; i < NCHUNK; i++) {
        CP_WAIT0();
        __syncthreads();
        if (i + 1 < NCHUNK) { load_stage((i + 1) & 1, i + 1); CP_COMMIT(); }

        uint32_t st = sb + (i & 1) * STAGE;
#pragma unroll
        for (int s = 0; s < 4; s++) {
            uint32_t sbyte = (uint32_t)(s * 32) + col16;
            uint32_t bh[6][2];
#pragma unroll
            for (int np = 0; np < 3; np++) {
                uint32_t rb = (uint32_t)(wn * 48 + np * 16) + row_add;
                uint32_t t0[4];
                ldsm4(t0, st + OFF_BH + rb * SSTRIDE + sbyte);
                bh[2 * np][0] = t0[0]; bh[2 * np][1] = t0[2];
                bh[2 * np + 1][0] = t0[1]; bh[2 * np + 1][1] = t0[3];
            }
#pragma unroll
            for (int f = 0; f < 4; f++) {
                uint32_t rr = (uint32_t)(wm * 64 + f * 16) + row_add;
                uint32_t ah[4], al[4];
                ldsm4(ah, st + OFF_AH + rr * SSTRIDE + sbyte);
                ldsm4(al, st + OFF_AL + rr * SSTRIDE + sbyte);
#pragma unroll
                for (int n = 0; n < 6; n++) {
                    mma_f16(c[f][n], ah, bh[n]);
                    mma_f16(c[f][n], al, bh[n]);
                }
            }
        }
    }

    int rbase = m0 + wm * 64 + (lane >> 2);
    int cbase = n0 + wn * 48 + (lane & 3) * 2;
    const float* be = bias + (size_t)e * NFULL;
#pragma unroll
    for (int f = 0; f < 4; f++) {
        int r0 = rbase + f * 16;
#pragma unroll
        for (int n = 0; n < 6; n++) {
            int gc = cbase + n * 8;
            float bx = be[gc], by = be[gc + 1];
            if (r0 < ne) {
                float2 v = make_float2(c[f][n][0] + bx, c[f][n][1] + by);
                *reinterpret_cast<float2*>(
                    C + (size_t)(e * TOK + r0) * NFULL + gc) = v;
            }
            if (r0 + 8 < ne) {
                float2 v = make_float2(c[f][n][2] + bx, c[f][n][3] + by);
                *reinterpret_cast<float2*>(
                    C + (size_t)(e * TOK + r0 + 8) * NFULL + gc) = v;
            }
        }
    }
}

// ---------------- clamped SwiGLU -> fp16 hi/lo ----------------
__device__ __forceinline__ float swi(float g, float l) {
    g = fminf(g, c_limit);
    l = fminf(fmaxf(l, -c_limit), c_limit);
    float s = 1.f / (1.f + expf(-c_alpha * g));
    return g * s * (l + 1.0f);
}
__global__ void swiglu_kernel() {
    int idx = blockIdx.x * blockDim.x + threadIdx.x;
    const int per_row = INTER / 4;
    if (idx >= MAXR * per_row) return;
    int r = idx / per_row;
    int c4 = idx - r * per_row;
    if ((r & (TOK - 1)) >= g_cnt[r / TOK]) return;
    size_t base = (size_t)r * N1 + (size_t)c4 * 4;
    float4 gv = *reinterpret_cast<const float4*>(&g_h[base]);
    float4 lv = *reinterpret_cast<const float4*>(&g_h[base + INTER]);
    float4 o;
    o.x = swi(gv.x, lv.x); o.y = swi(gv.y, lv.y);
    o.z = swi(gv.z, lv.z); o.w = swi(gv.w, lv.w);
    H4 h, l;
    split2h(o.x, h.h[0], l.h[0]); split2h(o.y, h.h[1], l.h[1]);
    split2h(o.z, h.h[2], l.h[2]); split2h(o.w, h.h[3], l.h[3]);
    size_t o8 = (size_t)r * (KDIM / 4) + c4;
    reinterpret_cast<unsigned long long*>(g_ah)[o8] = h.u;
    reinterpret_cast<unsigned long long*>(g_al)[o8] = l.u;
}

// ---------------- weighted combine ----------------
__global__ void combine_kernel(float* __restrict__ y) {
    int idx = blockIdx.x * blockDim.x + threadIdx.x;
    const int per_row = HID / 4;
    if (idx >= TOK * per_row) return;
    int t = idx / per_row;
    int c = (idx - t * per_row) * 4;
    float4 accv = make_float4(0.f, 0.f, 0.f, 0.f);
#pragma unroll
    for (int k = 0; k < TOPK; k++) {
        int p = g_pos[t][k];
        float wv = g_w[t][k];
        float4 v = *reinterpret_cast<const float4*>(&g_yp[(size_t)p * HID + c]);
        accv.x += wv * v.x; accv.y += wv * v.y;
        accv.z += wv * v.z; accv.w += wv * v.w;
    }
    *reinterpret_cast<float4*>(&y[(size_t)t * HID + c]) = accv;
}

// ---------------- launch ----------------
extern "C" void kernel_launch(void* const* d_in, const int* in_sizes, int n_in,
                              void* d_out, int out_size) {
    const float* x  = (const float*)d_in[0];
    const float* gw = (const float*)d_in[1];
    const float* gb = (const float*)d_in[2];
    const float* w1 = (const float*)d_in[3];
    const float* b1 = (const float*)d_in[4];
    const float* w2 = (const float*)d_in[5];
    const float* b2 = (const float*)d_in[6];
    float* y = (float*)d_out;

    cudaFuncSetAttribute(mma_gemm_kernel<true, N1>,
                         cudaFuncAttributeMaxDynamicSharedMemorySize, SMEM_GEMM);
    cudaFuncSetAttribute(mma_gemm_kernel<false, HID>,
                         cudaFuncAttributeMaxDynamicSharedMemorySize, SMEM_GEMM);

    init_kernel<<<1, 32>>>();
    router_kernel<<<TOK / 8, 256>>>(x, gw, gb);
    convert_x_kernel<<<(TOK * KDIM / 4 + 255) / 256, 256>>>(x);
    transpose_split_kernel<0><<<dim3(N1 / 32, KDIM / 32, NEXP), 256>>>(w1);
    transpose_split_kernel<1><<<dim3(HID / 32, KDIM / 32, NEXP), 256>>>(w2);

    mma_gemm_kernel<true, N1><<<dim3(16, 30, NEXP), 256, SMEM_GEMM>>>(b1);
    swiglu_kernel<<<(MAXR * (INTER / 4) + 255) / 256, 256>>>();
    mma_gemm_kernel<false, HID><<<dim3(16, 15, NEXP), 256, SMEM_GEMM>>>(b2);
    combine_kernel<<<(TOK * (HID / 4) + 255) / 256, 256>>>(y);
}

// round 7
// speedup vs baseline: 3.6246x; 1.1463x over previous
#include <cuda_runtime.h>
#include <cuda_fp16.h>
#include <cstdint>

#define TOK   2048
#define HID   2880
#define INTER 2880
#define NEXP  8
#define TOPK  4
#define N1    (2*INTER)        // 5760
#define MAXR  (NEXP*TOK)       // 16384
#define KDIM  2880

__device__ __constant__ float c_alpha = 1.702f;
__device__ __constant__ float c_limit = 7.0f;

// ---------------- static scratch ----------------
__device__ int   g_cnt[NEXP];
__device__ int   g_tok[NEXP][TOK];
__device__ int   g_pos[TOK][TOPK];
__device__ float g_w  [TOK][TOPK];
__device__ __align__(16) float g_h [(size_t)MAXR * N1];
__device__ __align__(16) float g_yp[(size_t)MAXR * HID];
__device__ __align__(16) __half g_xh [(size_t)TOK * KDIM];
__device__ __align__(16) __half g_xl [(size_t)TOK * KDIM];
__device__ __align__(16) __half g_w1h[(size_t)NEXP * N1 * KDIM];
__device__ __align__(16) __half g_w2h[(size_t)NEXP * HID * KDIM];
__device__ __align__(16) __half g_ah [(size_t)MAXR * KDIM];

// ---------------- helpers ----------------
__device__ __forceinline__ uint32_t smem_to_u32(const void* p) {
    uint32_t a;
    asm("{ .reg .u64 t; cvta.to.shared.u64 t, %1; cvt.u32.u64 %0, t; }"
        : "=r"(a) : "l"(p));
    return a;
}
__device__ __forceinline__ void ldsm4(uint32_t* r, uint32_t addr) {
    asm volatile("ldmatrix.sync.aligned.m8n8.x4.shared.b16 {%0,%1,%2,%3}, [%4];"
                 : "=r"(r[0]), "=r"(r[1]), "=r"(r[2]), "=r"(r[3])
                 : "r"(addr) : "memory");
}
__device__ __forceinline__ void mma_f16(float* c, const uint32_t* a, const uint32_t* b) {
    asm volatile(
        "mma.sync.aligned.m16n8k16.row.col.f32.f16.f16.f32 "
        "{%0,%1,%2,%3}, {%4,%5,%6,%7}, {%8,%9}, {%0,%1,%2,%3};"
        : "+f"(c[0]), "+f"(c[1]), "+f"(c[2]), "+f"(c[3])
        : "r"(a[0]), "r"(a[1]), "r"(a[2]), "r"(a[3]), "r"(b[0]), "r"(b[1]));
}
__device__ __forceinline__ void cpa16(uint32_t dst, const void* src) {
    asm volatile("cp.async.cg.shared.global [%0], [%1], 16;"
                 :: "r"(dst), "l"(src) : "memory");
}
#define CP_COMMIT() asm volatile("cp.async.commit_group;" ::: "memory")
#define CP_WAIT0()  asm volatile("cp.async.wait_group 0;" ::: "memory")

__device__ __forceinline__ void split2h(float v, __half& h, __half& l) {
    h = __float2half_rn(v);
    l = __float2half_rn(v - __half2float(h));
}
union H4 { unsigned long long u; __half h[4]; };

// ---------------- init ----------------
__global__ void init_kernel() {
    if (threadIdx.x < NEXP) g_cnt[threadIdx.x] = 0;
}

// ---------------- router ----------------
__global__ void router_kernel(const float* __restrict__ x,
                              const float* __restrict__ gw,
                              const float* __restrict__ gb) {
    int warp = threadIdx.x >> 5, lane = threadIdx.x & 31;
    int t = blockIdx.x * 8 + warp;
    if (t >= TOK) return;
    const float* xr = x + (size_t)t * HID;
    float acc[NEXP];
#pragma unroll
    for (int e = 0; e < NEXP; e++) acc[e] = 0.f;
    for (int h = lane; h < HID; h += 32) {
        float xv = xr[h];
        const float4* g4 = reinterpret_cast<const float4*>(gw + (size_t)h * NEXP);
        float4 ga = g4[0], gbv = g4[1];
        acc[0] += xv * ga.x;  acc[1] += xv * ga.y;
        acc[2] += xv * ga.z;  acc[3] += xv * ga.w;
        acc[4] += xv * gbv.x; acc[5] += xv * gbv.y;
        acc[6] += xv * gbv.z; acc[7] += xv * gbv.w;
    }
#pragma unroll
    for (int e = 0; e < NEXP; e++)
#pragma unroll
        for (int off = 16; off; off >>= 1)
            acc[e] += __shfl_xor_sync(0xffffffffu, acc[e], off);
    if (lane == 0) {
        float lg[NEXP];
#pragma unroll
        for (int e = 0; e < NEXP; e++) lg[e] = acc[e] + gb[e];
        int idx[TOPK]; float val[TOPK]; unsigned mask = 0;
#pragma unroll
        for (int k = 0; k < TOPK; k++) {
            float best = -3.4e38f; int bi = 0;
#pragma unroll
            for (int e = 0; e < NEXP; e++)
                if (!((mask >> e) & 1u) && lg[e] > best) { best = lg[e]; bi = e; }
            mask |= 1u << bi; idx[k] = bi; val[k] = best;
        }
        float m = val[0], s = 0.f, w[TOPK];
#pragma unroll
        for (int k = 0; k < TOPK; k++) { w[k] = expf(val[k] - m); s += w[k]; }
        float inv = 1.f / s;
#pragma unroll
        for (int k = 0; k < TOPK; k++) {
            int e = idx[k];
            int p = atomicAdd(&g_cnt[e], 1);
            g_tok[e][p] = t;
            g_pos[t][k] = e * TOK + p;
            g_w[t][k]   = w[k] * inv;
        }
    }
}

// ---------------- x -> fp16 hi/lo ----------------
__global__ void convert_x_kernel(const float* __restrict__ x) {
    size_t i4 = (size_t)blockIdx.x * blockDim.x + threadIdx.x;
    if (i4 >= (size_t)TOK * KDIM / 4) return;
    float4 v = reinterpret_cast<const float4*>(x)[i4];
    H4 h, l;
    split2h(v.x, h.h[0], l.h[0]); split2h(v.y, h.h[1], l.h[1]);
    split2h(v.z, h.h[2], l.h[2]); split2h(v.w, h.h[3], l.h[3]);
    reinterpret_cast<unsigned long long*>(g_xh)[i4] = h.u;
    reinterpret_cast<unsigned long long*>(g_xl)[i4] = l.u;
}

// ---------------- weight transpose + fp16 (hi only) ----------------
template<int WHICH>
__global__ void transpose_split_kernel(const float* __restrict__ W) {
    constexpr int Kd = KDIM;
    constexpr int Nd = WHICH ? HID : N1;
    __half* TH = WHICH ? g_w2h : g_w1h;       // device-code symbol ref
    __shared__ float t[32][33];
    int e = blockIdx.z;
    int n0 = blockIdx.x * 32, k0 = blockIdx.y * 32;
    int tx = threadIdx.x & 7, ty = threadIdx.x >> 3;
    float4 v = *reinterpret_cast<const float4*>(
        W + ((size_t)e * Kd + k0 + ty) * Nd + n0 + tx * 4);
    t[ty][tx * 4 + 0] = v.x; t[ty][tx * 4 + 1] = v.y;
    t[ty][tx * 4 + 2] = v.z; t[ty][tx * 4 + 3] = v.w;
    __syncthreads();
    H4 h;
#pragma unroll
    for (int j = 0; j < 4; j++) h.h[j] = __float2half_rn(t[tx * 4 + j][ty]);
    size_t off = ((size_t)e * Nd + n0 + ty) * Kd + k0 + tx * 4;
    *reinterpret_cast<unsigned long long*>(TH + off) = h.u;
}

// ---------------- mma.sync GEMM (fp16; optional A hi/lo 2-term) ----------
// CTA tile 128(m) x 192(n); warps 2m x 4n, warp tile 64x48; K chunk 64.
// SMEM padded rows (stride 144B, conflict-free); 2 stages.
#define KC      64
#define NCHUNK  (KDIM / KC)            // 45
#define SSTRIDE 144
#define OFF_AH  0
#define OFF_AL  18432
#define OFF_BH  36864
#define STAGE   64512
#define SMEM_GEMM (2 * STAGE + 512)    // 129536

template<bool FIRST, int NFULL, bool ALO>
__global__ __launch_bounds__(256, 1)
void mma_gemm_kernel(const float* __restrict__ bias) {
    extern __shared__ __align__(1024) char smem[];
    int tid = threadIdx.x;
    int e = blockIdx.z;
    int ne = g_cnt[e];
    int m0 = blockIdx.x * 128;
    if (m0 >= ne) return;
    int n0 = blockIdx.y * 192;

    const __half* Ah_ = FIRST ? g_xh : g_ah;
    const __half* Al_ = g_xl;                 // only used when ALO
    const __half* Bh_ = FIRST ? g_w1h : g_w2h;
    float* C = FIRST ? g_h : g_yp;

    int* rowid = reinterpret_cast<int*>(smem + 2 * STAGE);
    if (tid < 128) {
        int mi = m0 + tid; if (mi >= ne) mi = ne - 1;
        rowid[tid] = FIRST ? g_tok[e][mi] : (e * TOK + mi);
    }
    __syncthreads();

    uint32_t sb = smem_to_u32(smem);
    int r8  = tid >> 3;                // 0..31
    int seg = tid & 7;                 // 16B segment within 128B row
    size_t ebase = (size_t)e * NFULL + n0;
    int ra[4];
#pragma unroll
    for (int j = 0; j < 4; j++) ra[j] = rowid[r8 + 32 * j];

    auto load_stage = [&](int stg, int chunk) {
        uint32_t sbase = sb + stg * STAGE;
        size_t k0 = (size_t)chunk * KC + seg * 8;
#pragma unroll
        for (int j = 0; j < 4; j++) {
            uint32_t so = (uint32_t)(r8 + 32 * j) * SSTRIDE + seg * 16;
            cpa16(sbase + OFF_AH + so, Ah_ + (size_t)ra[j] * KDIM + k0);
            if (ALO)
                cpa16(sbase + OFF_AL + so, Al_ + (size_t)ra[j] * KDIM + k0);
        }
#pragma unroll
        for (int j = 0; j < 6; j++) {
            uint32_t so = (uint32_t)(r8 + 32 * j) * SSTRIDE + seg * 16;
            cpa16(sbase + OFF_BH + so,
                  Bh_ + (ebase + r8 + 32 * j) * KDIM + k0);
        }
    };

    int w = tid >> 5, lane = tid & 31;
    int wn = w & 3, wm = w >> 2;
    uint32_t row_add = (uint32_t)((lane & 7) + ((lane >> 3) & 1) * 8);
    uint32_t col16 = (uint32_t)(((lane >> 4) & 1) * 16);

    float c[4][6][4];
#pragma unroll
    for (int f = 0; f < 4; f++)
#pragma unroll
        for (int n = 0; n < 6; n++)
#pragma unroll
            for (int k = 0; k < 4; k++) c[f][n][k] = 0.f;

    load_stage(0, 0);
    CP_COMMIT();

    for (int i = 0; i < NCHUNK; i++) {
        CP_WAIT0();
        __syncthreads();
        if (i + 1 < NCHUNK) { load_stage((i + 1) & 1, i + 1); CP_COMMIT(); }

        uint32_t st = sb + (i & 1) * STAGE;
#pragma unroll
        for (int s = 0; s < 4; s++) {
            uint32_t sbyte = (uint32_t)(s * 32) + col16;
            uint32_t bh[6][2];
#pragma unroll
            for (int np = 0; np < 3; np++) {
                uint32_t rb = (uint32_t)(wn * 48 + np * 16) + row_add;
                uint32_t t0[4];
                ldsm4(t0, st + OFF_BH + rb * SSTRIDE + sbyte);
                bh[2 * np][0] = t0[0]; bh[2 * np][1] = t0[2];
                bh[2 * np + 1][0] = t0[1]; bh[2 * np + 1][1] = t0[3];
            }
#pragma unroll
            for (int f = 0; f < 4; f++) {
                uint32_t rr = (uint32_t)(wm * 64 + f * 16) + row_add;
                uint32_t ah[4];
                ldsm4(ah, st + OFF_AH + rr * SSTRIDE + sbyte);
                if (ALO) {
                    uint32_t al[4];
                    ldsm4(al, st + OFF_AL + rr * SSTRIDE + sbyte);
#pragma unroll
                    for (int n = 0; n < 6; n++) {
                        mma_f16(c[f][n], ah, bh[n]);
                        mma_f16(c[f][n], al, bh[n]);
                    }
                } else {
#pragma unroll
                    for (int n = 0; n < 6; n++)
                        mma_f16(c[f][n], ah, bh[n]);
                }
            }
        }
    }

    int rbase = m0 + wm * 64 + (lane >> 2);
    int cbase = n0 + wn * 48 + (lane & 3) * 2;
    const float* be = bias + (size_t)e * NFULL;
#pragma unroll
    for (int f = 0; f < 4; f++) {
        int r0 = rbase + f * 16;
#pragma unroll
        for (int n = 0; n < 6; n++) {
            int gc = cbase + n * 8;
            float bx = be[gc], by = be[gc + 1];
            if (r0 < ne) {
                float2 v = make_float2(c[f][n][0] + bx, c[f][n][1] + by);
                *reinterpret_cast<float2*>(
                    C + (size_t)(e * TOK + r0) * NFULL + gc) = v;
            }
            if (r0 + 8 < ne) {
                float2 v = make_float2(c[f][n][2] + bx, c[f][n][3] + by);
                *reinterpret_cast<float2*>(
                    C + (size_t)(e * TOK + r0 + 8) * NFULL + gc) = v;
            }
        }
    }
}

// ---------------- clamped SwiGLU -> fp16 (hi only) ----------------
__device__ __forceinline__ float swi(float g, float l) {
    g = fminf(g, c_limit);
    l = fminf(fmaxf(l, -c_limit), c_limit);
    float s = 1.f / (1.f + expf(-c_alpha * g));
    return g * s * (l + 1.0f);
}
__global__ void swiglu_kernel() {
    int idx = blockIdx.x * blockDim.x + threadIdx.x;
    const int per_row = INTER / 4;
    if (idx >= MAXR * per_row) return;
    int r = idx / per_row;
    int c4 = idx - r * per_row;
    if ((r & (TOK - 1)) >= g_cnt[r / TOK]) return;
    size_t base = (size_t)r * N1 + (size_t)c4 * 4;
    float4 gv = *reinterpret_cast<const float4*>(&g_h[base]);
    float4 lv = *reinterpret_cast<const float4*>(&g_h[base + INTER]);
    H4 h;
    h.h[0] = __float2half_rn(swi(gv.x, lv.x));
    h.h[1] = __float2half_rn(swi(gv.y, lv.y));
    h.h[2] = __float2half_rn(swi(gv.z, lv.z));
    h.h[3] = __float2half_rn(swi(gv.w, lv.w));
    reinterpret_cast<unsigned long long*>(g_ah)[(size_t)r * (KDIM / 4) + c4] = h.u;
}

// ---------------- weighted combine ----------------
__global__ void combine_kernel(float* __restrict__ y) {
    int idx = blockIdx.x * blockDim.x + threadIdx.x;
    const int per_row = HID / 4;
    if (idx >= TOK * per_row) return;
    int t = idx / per_row;
    int c = (idx - t * per_row) * 4;
    float4 accv = make_float4(0.f, 0.f, 0.f, 0.f);
#pragma unroll
    for (int k = 0; k < TOPK; k++) {
        int p = g_pos[t][k];
        float wv = g_w[t][k];
        float4 v = *reinterpret_cast<const float4*>(&g_yp[(size_t)p * HID + c]);
        accv.x += wv * v.x; accv.y += wv * v.y;
        accv.z += wv * v.z; accv.w += wv * v.w;
    }
    *reinterpret_cast<float4*>(&y[(size_t)t * HID + c]) = accv;
}

// ---------------- launch ----------------
extern "C" void kernel_launch(void* const* d_in, const int* in_sizes, int n_in,
                              void* d_out, int out_size) {
    const float* x  = (const float*)d_in[0];
    const float* gw = (const float*)d_in[1];
    const float* gb = (const float*)d_in[2];
    const float* w1 = (const float*)d_in[3];
    const float* b1 = (const float*)d_in[4];
    const float* w2 = (const float*)d_in[5];
    const float* b2 = (const float*)d_in[6];
    float* y = (float*)d_out;

    cudaFuncSetAttribute(mma_gemm_kernel<true, N1, true>,
                         cudaFuncAttributeMaxDynamicSharedMemorySize, SMEM_GEMM);
    cudaFuncSetAttribute(mma_gemm_kernel<false, HID, false>,
                         cudaFuncAttributeMaxDynamicSharedMemorySize, SMEM_GEMM);

    init_kernel<<<1, 32>>>();
    router_kernel<<<TOK / 8, 256>>>(x, gw, gb);
    convert_x_kernel<<<(TOK * KDIM / 4 + 255) / 256, 256>>>(x);
    transpose_split_kernel<0><<<dim3(N1 / 32, KDIM / 32, NEXP), 256>>>(w1);
    transpose_split_kernel<1><<<dim3(HID / 32, KDIM / 32, NEXP), 256>>>(w2);

    mma_gemm_kernel<true, N1, true><<<dim3(16, 30, NEXP), 256, SMEM_GEMM>>>(b1);
    swiglu_kernel<<<(MAXR * (INTER / 4) + 255) / 256, 256>>>();
    mma_gemm_kernel<false, HID, false><<<dim3(16, 15, NEXP), 256, SMEM_GEMM>>>(b2);
    combine_kernel<<<(TOK * (HID / 4) + 255) / 256, 256>>>(y);
}

// round 8
// speedup vs baseline: 5.1403x; 1.4182x over previous
#include <cuda_runtime.h>
#include <cuda_fp16.h>
#include <cstdint>

#define TOK   2048
#define HID   2880
#define INTER 2880
#define NEXP  8
#define TOPK  4
#define N1    (2*INTER)        // 5760
#define MAXR  (NEXP*TOK)       // 16384
#define KDIM  2880

__device__ __constant__ float c_alpha = 1.702f;
__device__ __constant__ float c_limit = 7.0f;

// ---------------- static scratch ----------------
__device__ int   g_cnt[NEXP];
__device__ int   g_tok[NEXP][TOK];
__device__ int   g_pos[TOK][TOPK];
__device__ float g_w  [TOK][TOPK];
__device__ __align__(16) float g_h [(size_t)MAXR * N1];
__device__ __align__(16) float g_yp[(size_t)MAXR * HID];
__device__ __align__(16) __half g_xh [(size_t)TOK * KDIM];
__device__ __align__(16) __half g_xl [(size_t)TOK * KDIM];   // kept for ALO revert path
__device__ __align__(16) __half g_w1h[(size_t)NEXP * N1 * KDIM];
__device__ __align__(16) __half g_w2h[(size_t)NEXP * HID * KDIM];
__device__ __align__(16) __half g_ah [(size_t)MAXR * KDIM];

// ---------------- helpers ----------------
__device__ __forceinline__ uint32_t smem_to_u32(const void* p) {
    uint32_t a;
    asm("{ .reg .u64 t; cvta.to.shared.u64 t, %1; cvt.u32.u64 %0, t; }"
        : "=r"(a) : "l"(p));
    return a;
}
__device__ __forceinline__ void ldsm4(uint32_t* r, uint32_t addr) {
    asm volatile("ldmatrix.sync.aligned.m8n8.x4.shared.b16 {%0,%1,%2,%3}, [%4];"
                 : "=r"(r[0]), "=r"(r[1]), "=r"(r[2]), "=r"(r[3])
                 : "r"(addr) : "memory");
}
__device__ __forceinline__ void mma_f16(float* c, const uint32_t* a, const uint32_t* b) {
    asm volatile(
        "mma.sync.aligned.m16n8k16.row.col.f32.f16.f16.f32 "
        "{%0,%1,%2,%3}, {%4,%5,%6,%7}, {%8,%9}, {%0,%1,%2,%3};"
        : "+f"(c[0]), "+f"(c[1]), "+f"(c[2]), "+f"(c[3])
        : "r"(a[0]), "r"(a[1]), "r"(a[2]), "r"(a[3]), "r"(b[0]), "r"(b[1]));
}
__device__ __forceinline__ void cpa16(uint32_t dst, const void* src) {
    asm volatile("cp.async.cg.shared.global [%0], [%1], 16;"
                 :: "r"(dst), "l"(src) : "memory");
}
#define CP_COMMIT() asm volatile("cp.async.commit_group;" ::: "memory")
#define CP_WAIT0()  asm volatile("cp.async.wait_group 0;" ::: "memory")

__device__ __forceinline__ void split2h(float v, __half& h, __half& l) {
    h = __float2half_rn(v);
    l = __float2half_rn(v - __half2float(h));
}
union H4 { unsigned long long u; __half h[4]; };

// ---------------- init ----------------
__global__ void init_kernel() {
    if (threadIdx.x < NEXP) g_cnt[threadIdx.x] = 0;
}

// ---------------- router ----------------
__global__ void router_kernel(const float* __restrict__ x,
                              const float* __restrict__ gw,
                              const float* __restrict__ gb) {
    int warp = threadIdx.x >> 5, lane = threadIdx.x & 31;
    int t = blockIdx.x * 8 + warp;
    if (t >= TOK) return;
    const float* xr = x + (size_t)t * HID;
    float acc[NEXP];
#pragma unroll
    for (int e = 0; e < NEXP; e++) acc[e] = 0.f;
    for (int h = lane; h < HID; h += 32) {
        float xv = xr[h];
        const float4* g4 = reinterpret_cast<const float4*>(gw + (size_t)h * NEXP);
        float4 ga = g4[0], gbv = g4[1];
        acc[0] += xv * ga.x;  acc[1] += xv * ga.y;
        acc[2] += xv * ga.z;  acc[3] += xv * ga.w;
        acc[4] += xv * gbv.x; acc[5] += xv * gbv.y;
        acc[6] += xv * gbv.z; acc[7] += xv * gbv.w;
    }
#pragma unroll
    for (int e = 0; e < NEXP; e++)
#pragma unroll
        for (int off = 16; off; off >>= 1)
            acc[e] += __shfl_xor_sync(0xffffffffu, acc[e], off);
    if (lane == 0) {
        float lg[NEXP];
#pragma unroll
        for (int e = 0; e < NEXP; e++) lg[e] = acc[e] + gb[e];
        int idx[TOPK]; float val[TOPK]; unsigned mask = 0;
#pragma unroll
        for (int k = 0; k < TOPK; k++) {
            float best = -3.4e38f; int bi = 0;
#pragma unroll
            for (int e = 0; e < NEXP; e++)
                if (!((mask >> e) & 1u) && lg[e] > best) { best = lg[e]; bi = e; }
            mask |= 1u << bi; idx[k] = bi; val[k] = best;
        }
        float m = val[0], s = 0.f, w[TOPK];
#pragma unroll
        for (int k = 0; k < TOPK; k++) { w[k] = expf(val[k] - m); s += w[k]; }
        float inv = 1.f / s;
#pragma unroll
        for (int k = 0; k < TOPK; k++) {
            int e = idx[k];
            int p = atomicAdd(&g_cnt[e], 1);
            g_tok[e][p] = t;
            g_pos[t][k] = e * TOK + p;
            g_w[t][k]   = w[k] * inv;
        }
    }
}

// ---------------- x -> fp16 (hi only) ----------------
__global__ void convert_x_kernel(const float* __restrict__ x) {
    size_t i4 = (size_t)blockIdx.x * blockDim.x + threadIdx.x;
    if (i4 >= (size_t)TOK * KDIM / 4) return;
    float4 v = reinterpret_cast<const float4*>(x)[i4];
    H4 h;
    h.h[0] = __float2half_rn(v.x); h.h[1] = __float2half_rn(v.y);
    h.h[2] = __float2half_rn(v.z); h.h[3] = __float2half_rn(v.w);
    reinterpret_cast<unsigned long long*>(g_xh)[i4] = h.u;
}

// ---------------- weight transpose + fp16 (hi only) ----------------
template<int WHICH>
__global__ void transpose_split_kernel(const float* __restrict__ W) {
    constexpr int Kd = KDIM;
    constexpr int Nd = WHICH ? HID : N1;
    __half* TH = WHICH ? g_w2h : g_w1h;       // device-code symbol ref
    __shared__ float t[32][33];
    int e = blockIdx.z;
    int n0 = blockIdx.x * 32, k0 = blockIdx.y * 32;
    int tx = threadIdx.x & 7, ty = threadIdx.x >> 3;
    float4 v = *reinterpret_cast<const float4*>(
        W + ((size_t)e * Kd + k0 + ty) * Nd + n0 + tx * 4);
    t[ty][tx * 4 + 0] = v.x; t[ty][tx * 4 + 1] = v.y;
    t[ty][tx * 4 + 2] = v.z; t[ty][tx * 4 + 3] = v.w;
    __syncthreads();
    H4 h;
#pragma unroll
    for (int j = 0; j < 4; j++) h.h[j] = __float2half_rn(t[tx * 4 + j][ty]);
    size_t off = ((size_t)e * Nd + n0 + ty) * Kd + k0 + tx * 4;
    *reinterpret_cast<unsigned long long*>(TH + off) = h.u;
}

// ---------------- mma.sync GEMM (fp16; optional A hi/lo 2-term) ----------
// CTA tile 128(m) x 192(n); warps 2m x 4n, warp tile 64x48; K chunk 64.
// SMEM padded rows (stride 144B, conflict-free); 2 stages.
#define KC      64
#define NCHUNK  (KDIM / KC)            // 45
#define SSTRIDE 144
#define OFF_AH  0
#define OFF_AL  18432
#define OFF_BH  36864
#define STAGE   64512
#define SMEM_GEMM (2 * STAGE + 512)    // 129536

template<bool FIRST, int NFULL, bool ALO>
__global__ __launch_bounds__(256, 1)
void mma_gemm_kernel(const float* __restrict__ bias) {
    extern __shared__ __align__(1024) char smem[];
    int tid = threadIdx.x;
    int e = blockIdx.z;
    int ne = g_cnt[e];
    int m0 = blockIdx.x * 128;
    if (m0 >= ne) return;
    int n0 = blockIdx.y * 192;

    const __half* Ah_ = FIRST ? g_xh : g_ah;
    const __half* Al_ = g_xl;                 // only used when ALO
    const __half* Bh_ = FIRST ? g_w1h : g_w2h;
    float* C = FIRST ? g_h : g_yp;

    int* rowid = reinterpret_cast<int*>(smem + 2 * STAGE);
    if (tid < 128) {
        int mi = m0 + tid; if (mi >= ne) mi = ne - 1;
        rowid[tid] = FIRST ? g_tok[e][mi] : (e * TOK + mi);
    }
    __syncthreads();

    uint32_t sb = smem_to_u32(smem);
    int r8  = tid >> 3;                // 0..31
    int seg = tid & 7;                 // 16B segment within 128B row
    size_t ebase = (size_t)e * NFULL + n0;
    int ra[4];
#pragma unroll
    for (int j = 0; j < 4; j++) ra[j] = rowid[r8 + 32 * j];

    auto load_stage = [&](int stg, int chunk) {
        uint32_t sbase = sb + stg * STAGE;
        size_t k0 = (size_t)chunk * KC + seg * 8;
#pragma unroll
        for (int j = 0; j < 4; j++) {
            uint32_t so = (uint32_t)(r8 + 32 * j) * SSTRIDE + seg * 16;
            cpa16(sbase + OFF_AH + so, Ah_ + (size_t)ra[j] * KDIM + k0);
            if (ALO)
                cpa16(sbase + OFF_AL + so, Al_ + (size_t)ra[j] * KDIM + k0);
        }
#pragma unroll
        for (int j = 0; j < 6; j++) {
            uint32_t so = (uint32_t)(r8 + 32 * j) * SSTRIDE + seg * 16;
            cpa16(sbase + OFF_BH + so,
                  Bh_ + (ebase + r8 + 32 * j) * KDIM + k0);
        }
    };

    int w = tid >> 5, lane = tid & 31;
    int wn = w & 3, wm = w >> 2;
    uint32_t row_add = (uint32_t)((lane & 7) + ((lane >> 3) & 1) * 8);
    uint32_t col16 = (uint32_t)(((lane >> 4) & 1) * 16);

    float c[4][6][4];
#pragma unroll
    for (int f = 0; f < 4; f++)
#pragma unroll
        for (int n = 0; n < 6; n++)
#pragma unroll
            for (int k = 0; k < 4; k++) c[f][n][k] = 0.f;

    load_stage(0, 0);
    CP_COMMIT();

    for (int i = 0; i < NCHUNK; i++) {
        CP_WAIT0();
        __syncthreads();
        if (i + 1 < NCHUNK) { load_stage((i + 1) & 1, i + 1); CP_COMMIT(); }

        uint32_t st = sb + (i & 1) * STAGE;
#pragma unroll
        for (int s = 0; s < 4; s++) {
            uint32_t sbyte = (uint32_t)(s * 32) + col16;
            uint32_t bh[6][2];
#pragma unroll
            for (int np = 0; np < 3; np++) {
                uint32_t rb = (uint32_t)(wn * 48 + np * 16) + row_add;
                uint32_t t0[4];
                ldsm4(t0, st + OFF_BH + rb * SSTRIDE + sbyte);
                bh[2 * np][0] = t0[0]; bh[2 * np][1] = t0[2];
                bh[2 * np + 1][0] = t0[1]; bh[2 * np + 1][1] = t0[3];
            }
#pragma unroll
            for (int f = 0; f < 4; f++) {
                uint32_t rr = (uint32_t)(wm * 64 + f * 16) + row_add;
                uint32_t ah[4];
                ldsm4(ah, st + OFF_AH + rr * SSTRIDE + sbyte);
                if (ALO) {
                    uint32_t al[4];
                    ldsm4(al, st + OFF_AL + rr * SSTRIDE + sbyte);
#pragma unroll
                    for (int n = 0; n < 6; n++) {
                        mma_f16(c[f][n], ah, bh[n]);
                        mma_f16(c[f][n], al, bh[n]);
                    }
                } else {
#pragma unroll
                    for (int n = 0; n < 6; n++)
                        mma_f16(c[f][n], ah, bh[n]);
                }
            }
        }
    }

    int rbase = m0 + wm * 64 + (lane >> 2);
    int cbase = n0 + wn * 48 + (lane & 3) * 2;
    const float* be = bias + (size_t)e * NFULL;
#pragma unroll
    for (int f = 0; f < 4; f++) {
        int r0 = rbase + f * 16;
#pragma unroll
        for (int n = 0; n < 6; n++) {
            int gc = cbase + n * 8;
            float bx = be[gc], by = be[gc + 1];
            if (r0 < ne) {
                float2 v = make_float2(c[f][n][0] + bx, c[f][n][1] + by);
                *reinterpret_cast<float2*>(
                    C + (size_t)(e * TOK + r0) * NFULL + gc) = v;
            }
            if (r0 + 8 < ne) {
                float2 v = make_float2(c[f][n][2] + bx, c[f][n][3] + by);
                *reinterpret_cast<float2*>(
                    C + (size_t)(e * TOK + r0 + 8) * NFULL + gc) = v;
            }
        }
    }
}

// ---------------- clamped SwiGLU -> fp16 (hi only) ----------------
__device__ __forceinline__ float swi(float g, float l) {
    g = fminf(g, c_limit);
    l = fminf(fmaxf(l, -c_limit), c_limit);
    float s = 1.f / (1.f + expf(-c_alpha * g));
    return g * s * (l + 1.0f);
}
__global__ void swiglu_kernel() {
    int idx = blockIdx.x * blockDim.x + threadIdx.x;
    const int per_row = INTER / 4;
    if (idx >= MAXR * per_row) return;
    int r = idx / per_row;
    int c4 = idx - r * per_row;
    if ((r & (TOK - 1)) >= g_cnt[r / TOK]) return;
    size_t base = (size_t)r * N1 + (size_t)c4 * 4;
    float4 gv = *reinterpret_cast<const float4*>(&g_h[base]);
    float4 lv = *reinterpret_cast<const float4*>(&g_h[base + INTER]);
    H4 h;
    h.h[0] = __float2half_rn(swi(gv.x, lv.x));
    h.h[1] = __float2half_rn(swi(gv.y, lv.y));
    h.h[2] = __float2half_rn(swi(gv.z, lv.z));
    h.h[3] = __float2half_rn(swi(gv.w, lv.w));
    reinterpret_cast<unsigned long long*>(g_ah)[(size_t)r * (KDIM / 4) + c4] = h.u;
}

// ---------------- weighted combine ----------------
__global__ void combine_kernel(float* __restrict__ y) {
    int idx = blockIdx.x * blockDim.x + threadIdx.x;
    const int per_row = HID / 4;
    if (idx >= TOK * per_row) return;
    int t = idx / per_row;
    int c = (idx - t * per_row) * 4;
    float4 accv = make_float4(0.f, 0.f, 0.f, 0.f);
#pragma unroll
    for (int k = 0; k < TOPK; k++) {
        int p = g_pos[t][k];
        float wv = g_w[t][k];
        float4 v = *reinterpret_cast<const float4*>(&g_yp[(size_t)p * HID + c]);
        accv.x += wv * v.x; accv.y += wv * v.y;
        accv.z += wv * v.z; accv.w += wv * v.w;
    }
    *reinterpret_cast<float4*>(&y[(size_t)t * HID + c]) = accv;
}

// ---------------- launch ----------------
extern "C" void kernel_launch(void* const* d_in, const int* in_sizes, int n_in,
                              void* d_out, int out_size) {
    const float* x  = (const float*)d_in[0];
    const float* gw = (const float*)d_in[1];
    const float* gb = (const float*)d_in[2];
    const float* w1 = (const float*)d_in[3];
    const float* b1 = (const float*)d_in[4];
    const float* w2 = (const float*)d_in[5];
    const float* b2 = (const float*)d_in[6];
    float* y = (float*)d_out;

    cudaFuncSetAttribute(mma_gemm_kernel<true, N1, false>,
                         cudaFuncAttributeMaxDynamicSharedMemorySize, SMEM_GEMM);
    cudaFuncSetAttribute(mma_gemm_kernel<false, HID, false>,
                         cudaFuncAttributeMaxDynamicSharedMemorySize, SMEM_GEMM);

    init_kernel<<<1, 32>>>();
    router_kernel<<<TOK / 8, 256>>>(x, gw, gb);
    convert_x_kernel<<<(TOK * KDIM / 4 + 255) / 256, 256>>>(x);
    transpose_split_kernel<0><<<dim3(N1 / 32, KDIM / 32, NEXP), 256>>>(w1);
    transpose_split_kernel<1><<<dim3(HID / 32, KDIM / 32, NEXP), 256>>>(w2);

    mma_gemm_kernel<true, N1, false><<<dim3(16, 30, NEXP), 256, SMEM_GEMM>>>(b1);
    swiglu_kernel<<<(MAXR * (INTER / 4) + 255) / 256, 256>>>();
    mma_gemm_kernel<false, HID, false><<<dim3(16, 15, NEXP), 256, SMEM_GEMM>>>(b2);
    combine_kernel<<<(TOK * (HID / 4) + 255) / 256, 256>>>(y);
}

// round 9
// speedup vs baseline: 5.5393x; 1.0776x over previous
#include <cuda_runtime.h>
#include <cuda_fp16.h>
#include <cstdint>

#define TOK   2048
#define HID   2880
#define INTER 2880
#define NEXP  8
#define TOPK  4
#define N1    (2*INTER)        // 5760
#define MAXR  (NEXP*TOK)       // 16384
#define KDIM  2880

__device__ __constant__ float c_alpha = 1.702f;
__device__ __constant__ float c_limit = 7.0f;

// ---------------- static scratch ----------------
__device__ int   g_cnt[NEXP];
__device__ int   g_tok[NEXP][TOK];
__device__ int   g_pos[TOK][TOPK];
__device__ float g_w  [TOK][TOPK];
__device__ __align__(16) float  g_yp [(size_t)MAXR * HID];
__device__ __align__(16) __half g_xh [(size_t)TOK * KDIM];
__device__ __align__(16) __half g_w1h[(size_t)NEXP * KDIM * N1];   // [e][k][n]
__device__ __align__(16) __half g_w2h[(size_t)NEXP * KDIM * HID];  // [e][k][n]
__device__ __align__(16) __half g_ah [(size_t)MAXR * KDIM];

// ---------------- helpers ----------------
__device__ __forceinline__ uint32_t smem_to_u32(const void* p) {
    uint32_t a;
    asm("{ .reg .u64 t; cvta.to.shared.u64 t, %1; cvt.u32.u64 %0, t; }"
        : "=r"(a) : "l"(p));
    return a;
}
__device__ __forceinline__ void ldsm4(uint32_t* r, uint32_t addr) {
    asm volatile("ldmatrix.sync.aligned.m8n8.x4.shared.b16 {%0,%1,%2,%3}, [%4];"
                 : "=r"(r[0]), "=r"(r[1]), "=r"(r[2]), "=r"(r[3])
                 : "r"(addr) : "memory");
}
__device__ __forceinline__ void ldsm4t(uint32_t* r, uint32_t addr) {
    asm volatile("ldmatrix.sync.aligned.m8n8.x4.trans.shared.b16 {%0,%1,%2,%3}, [%4];"
                 : "=r"(r[0]), "=r"(r[1]), "=r"(r[2]), "=r"(r[3])
                 : "r"(addr) : "memory");
}
__device__ __forceinline__ void ldsm2t(uint32_t* r, uint32_t addr) {
    asm volatile("ldmatrix.sync.aligned.m8n8.x2.trans.shared.b16 {%0,%1}, [%2];"
                 : "=r"(r[0]), "=r"(r[1])
                 : "r"(addr) : "memory");
}
__device__ __forceinline__ void mma_f16(float* c, const uint32_t* a, const uint32_t* b) {
    asm volatile(
        "mma.sync.aligned.m16n8k16.row.col.f32.f16.f16.f32 "
        "{%0,%1,%2,%3}, {%4,%5,%6,%7}, {%8,%9}, {%0,%1,%2,%3};"
        : "+f"(c[0]), "+f"(c[1]), "+f"(c[2]), "+f"(c[3])
        : "r"(a[0]), "r"(a[1]), "r"(a[2]), "r"(a[3]), "r"(b[0]), "r"(b[1]));
}
__device__ __forceinline__ void cpa16(uint32_t dst, const void* src) {
    asm volatile("cp.async.cg.shared.global [%0], [%1], 16;"
                 :: "r"(dst), "l"(src) : "memory");
}
#define CP_COMMIT() asm volatile("cp.async.commit_group;" ::: "memory")
#define CP_WAIT0()  asm volatile("cp.async.wait_group 0;" ::: "memory")

union H4 { unsigned long long u; __half h[4]; };

// ---------------- init ----------------
__global__ void init_kernel() {
    if (threadIdx.x < NEXP) g_cnt[threadIdx.x] = 0;
}

// ---------------- router ----------------
__global__ void router_kernel(const float* __restrict__ x,
                              const float* __restrict__ gw,
                              const float* __restrict__ gb) {
    int warp = threadIdx.x >> 5, lane = threadIdx.x & 31;
    int t = blockIdx.x * 8 + warp;
    if (t >= TOK) return;
    const float* xr = x + (size_t)t * HID;
    float acc[NEXP];
#pragma unroll
    for (int e = 0; e < NEXP; e++) acc[e] = 0.f;
    for (int h = lane; h < HID; h += 32) {
        float xv = xr[h];
        const float4* g4 = reinterpret_cast<const float4*>(gw + (size_t)h * NEXP);
        float4 ga = g4[0], gbv = g4[1];
        acc[0] += xv * ga.x;  acc[1] += xv * ga.y;
        acc[2] += xv * ga.z;  acc[3] += xv * ga.w;
        acc[4] += xv * gbv.x; acc[5] += xv * gbv.y;
        acc[6] += xv * gbv.z; acc[7] += xv * gbv.w;
    }
#pragma unroll
    for (int e = 0; e < NEXP; e++)
#pragma unroll
        for (int off = 16; off; off >>= 1)
            acc[e] += __shfl_xor_sync(0xffffffffu, acc[e], off);
    if (lane == 0) {
        float lg[NEXP];
#pragma unroll
        for (int e = 0; e < NEXP; e++) lg[e] = acc[e] + gb[e];
        int idx[TOPK]; float val[TOPK]; unsigned mask = 0;
#pragma unroll
        for (int k = 0; k < TOPK; k++) {
            float best = -3.4e38f; int bi = 0;
#pragma unroll
            for (int e = 0; e < NEXP; e++)
                if (!((mask >> e) & 1u) && lg[e] > best) { best = lg[e]; bi = e; }
            mask |= 1u << bi; idx[k] = bi; val[k] = best;
        }
        float m = val[0], s = 0.f, w[TOPK];
#pragma unroll
        for (int k = 0; k < TOPK; k++) { w[k] = expf(val[k] - m); s += w[k]; }
        float inv = 1.f / s;
#pragma unroll
        for (int k = 0; k < TOPK; k++) {
            int e = idx[k];
            int p = atomicAdd(&g_cnt[e], 1);
            g_tok[e][p] = t;
            g_pos[t][k] = e * TOK + p;
            g_w[t][k]   = w[k] * inv;
        }
    }
}

// ---------------- x -> fp16 ----------------
__global__ void convert_x_kernel(const float* __restrict__ x) {
    size_t i4 = (size_t)blockIdx.x * blockDim.x + threadIdx.x;
    if (i4 >= (size_t)TOK * KDIM / 4) return;
    float4 v = reinterpret_cast<const float4*>(x)[i4];
    H4 h;
    h.h[0] = __float2half_rn(v.x); h.h[1] = __float2half_rn(v.y);
    h.h[2] = __float2half_rn(v.z); h.h[3] = __float2half_rn(v.w);
    reinterpret_cast<unsigned long long*>(g_xh)[i4] = h.u;
}

// ---------------- weights -> fp16, layout preserved [e][k][n] ----------------
template<int WHICH>
__global__ void convert_w_kernel(const float* __restrict__ W) {
    __half* TH = WHICH ? g_w2h : g_w1h;   // device-code symbol ref
    const size_t n4 = ((size_t)NEXP * KDIM * (WHICH ? HID : N1)) / 4;
    size_t i4 = (size_t)blockIdx.x * blockDim.x + threadIdx.x;
    if (i4 >= n4) return;
    float4 v = reinterpret_cast<const float4*>(W)[i4];
    H4 h;
    h.h[0] = __float2half_rn(v.x); h.h[1] = __float2half_rn(v.y);
    h.h[2] = __float2half_rn(v.z); h.h[3] = __float2half_rn(v.w);
    reinterpret_cast<unsigned long long*>(TH)[i4] = h.u;
}

// ---------------- clamped SwiGLU scalar ----------------
__device__ __forceinline__ float swi(float g, float l) {
    g = fminf(g, c_limit);
    l = fminf(fmaxf(l, -c_limit), c_limit);
    float s = 1.f / (1.f + expf(-c_alpha * g));
    return g * s * (l + 1.0f);
}

// ---------------- fused GEMM (fp16 mma.sync, B k-major via ldmatrix.trans) --
// FIRST: A=g_xh gathered, B=w1h; CTA tile 128m x (96 glu + 96 lin);
//        epilogue = bias + swiglu -> g_ah (fp16).
// else : A=g_ah, B=w2h; CTA tile 128m x 192n; epilogue = bias -> g_yp (fp32).
// SMEM: A [128 rows][144B], B [64 k-rows][400B]; 2-stage cp.async.
#define KC      64
#define NCHUNK  (KDIM / KC)            // 45
#define ASTRIDE 144
#define BSTRIDE 400
#define OFF_B   18432
#define STAGE   (18432 + 25600)       // 44032
#define SMEM_GEMM (2 * STAGE + 512)    // 88576

template<bool FIRST>
__global__ __launch_bounds__(256, 1)
void mma_gemm_kernel(const float* __restrict__ bias) {
    extern __shared__ __align__(1024) char smem[];
    int tid = threadIdx.x;
    int e = blockIdx.z;
    int ne = g_cnt[e];
    int m0 = blockIdx.x * 128;
    if (m0 >= ne) return;
    constexpr int NW = FIRST ? N1 : HID;     // B row width in gmem
    int n0 = blockIdx.y * (FIRST ? 96 : 192);

    const __half* Ah_ = FIRST ? g_xh : g_ah;
    const __half* Bh_ = FIRST ? g_w1h : g_w2h;

    int* rowid = reinterpret_cast<int*>(smem + 2 * STAGE);
    if (tid < 128) {
        int mi = m0 + tid; if (mi >= ne) mi = ne - 1;
        rowid[tid] = FIRST ? g_tok[e][mi] : (e * TOK + mi);
    }
    __syncthreads();

    uint32_t sb = smem_to_u32(smem);
    int r8  = tid >> 3;                // 0..31
    int seg = tid & 7;
    int ra[4];
#pragma unroll
    for (int j = 0; j < 4; j++) ra[j] = rowid[r8 + 32 * j];

    // B loader slots: 6 granules, id = tid + j*256; row = id/24, g = id%24
    const __half* Be = Bh_ + (size_t)e * KDIM * NW;

    auto load_stage = [&](int stg, int chunk) {
        uint32_t sbase = sb + stg * STAGE;
        int kg0 = chunk * KC;
#pragma unroll
        for (int j = 0; j < 4; j++) {
            uint32_t so = (uint32_t)(r8 + 32 * j) * ASTRIDE + seg * 16;
            cpa16(sbase + so, Ah_ + (size_t)ra[j] * KDIM + kg0 + seg * 8);
        }
#pragma unroll
        for (int j = 0; j < 6; j++) {
            int id = tid + j * 256;
            int row = id / 24, g = id - row * 24;
            int col;
            if (FIRST) col = (g < 12) ? (n0 + g * 8) : (INTER + n0 + (g - 12) * 8);
            else       col = n0 + g * 8;
            cpa16(sbase + OFF_B + (uint32_t)row * BSTRIDE + g * 16,
                  Be + (size_t)(kg0 + row) * NW + col);
        }
    };

    int w = tid >> 5, lane = tid & 31;
    int wn = w & 3, wm = w >> 2;
    uint32_t row_add = (uint32_t)((lane & 7) + ((lane >> 3) & 1) * 8);
    uint32_t col16 = (uint32_t)(((lane >> 4) & 1) * 16);
    // B ldmatrix.trans addressing: krow within chunk, ncol in smem col space
    uint32_t bk_add = (uint32_t)((lane & 7) + ((lane >> 3) & 1) * 8);
    uint32_t bn8 = (uint32_t)((lane >> 4) * 8);

    float c[4][6][4];
#pragma unroll
    for (int f = 0; f < 4; f++)
#pragma unroll
        for (int n = 0; n < 6; n++)
#pragma unroll
            for (int k = 0; k < 4; k++) c[f][n][k] = 0.f;

    load_stage(0, 0);
    CP_COMMIT();

    for (int i = 0; i < NCHUNK; i++) {
        CP_WAIT0();
        __syncthreads();
        if (i + 1 < NCHUNK) { load_stage((i + 1) & 1, i + 1); CP_COMMIT(); }

        uint32_t st = sb + (i & 1) * STAGE;
#pragma unroll
        for (int s = 0; s < 4; s++) {
            uint32_t brow = st + OFF_B + (s * 16 + bk_add) * BSTRIDE;
            uint32_t bh[6][2];
            if (FIRST) {
                // glu: cols 24*wn + {0..15} via x4, {16..23} via x2
                uint32_t t4[4], t2[2];
                ldsm4t(t4, brow + (uint32_t)(wn * 24) * 2 + bn8 * 2);
                bh[0][0] = t4[0]; bh[0][1] = t4[1];
                bh[1][0] = t4[2]; bh[1][1] = t4[3];
                ldsm2t(t2, brow + (uint32_t)(wn * 24 + 16) * 2);
                bh[2][0] = t2[0]; bh[2][1] = t2[1];
                // lin: smem cols 96 + 24*wn + ...
                ldsm4t(t4, brow + (uint32_t)(96 + wn * 24) * 2 + bn8 * 2);
                bh[3][0] = t4[0]; bh[3][1] = t4[1];
                bh[4][0] = t4[2]; bh[4][1] = t4[3];
                ldsm2t(t2, brow + (uint32_t)(96 + wn * 24 + 16) * 2);
                bh[5][0] = t2[0]; bh[5][1] = t2[1];
            } else {
#pragma unroll
                for (int q = 0; q < 3; q++) {
                    uint32_t t4[4];
                    ldsm4t(t4, brow + (uint32_t)(wn * 48 + q * 16) * 2 + bn8 * 2);
                    bh[2 * q][0] = t4[0];     bh[2 * q][1] = t4[1];
                    bh[2 * q + 1][0] = t4[2]; bh[2 * q + 1][1] = t4[3];
                }
            }
#pragma unroll
            for (int f = 0; f < 4; f++) {
                uint32_t rr = (uint32_t)(wm * 64 + f * 16) + row_add;
                uint32_t ah[4];
                ldsm4(ah, st + rr * ASTRIDE + (uint32_t)(s * 32) + col16);
#pragma unroll
                for (int n = 0; n < 6; n++)
                    mma_f16(c[f][n], ah, bh[n]);
            }
        }
    }

    int rbase = m0 + wm * 64 + (lane >> 2);
    if (FIRST) {
        const float* be = bias + (size_t)e * N1;
#pragma unroll
        for (int f = 0; f < 4; f++) {
            int r0 = rbase + f * 16;
#pragma unroll
            for (int j = 0; j < 3; j++) {
                int gc = n0 + wn * 24 + j * 8 + (lane & 3) * 2;
                float bg0 = be[gc], bg1 = be[gc + 1];
                float bl0 = be[INTER + gc], bl1 = be[INTER + gc + 1];
                if (r0 < ne) {
                    float a0 = swi(c[f][j][0] + bg0, c[f][j + 3][0] + bl0);
                    float a1 = swi(c[f][j][1] + bg1, c[f][j + 3][1] + bl1);
                    *reinterpret_cast<__half2*>(
                        g_ah + (size_t)(e * TOK + r0) * KDIM + gc) =
                        __floats2half2_rn(a0, a1);
                }
                if (r0 + 8 < ne) {
                    float a0 = swi(c[f][j][2] + bg0, c[f][j + 3][2] + bl0);
                    float a1 = swi(c[f][j][3] + bg1, c[f][j + 3][3] + bl1);
                    *reinterpret_cast<__half2*>(
                        g_ah + (size_t)(e * TOK + r0 + 8) * KDIM + gc) =
                        __floats2half2_rn(a0, a1);
                }
            }
        }
    } else {
        const float* be = bias + (size_t)e * HID;
#pragma unroll
        for (int f = 0; f < 4; f++) {
            int r0 = rbase + f * 16;
#pragma unroll
            for (int n = 0; n < 6; n++) {
                int gc = n0 + wn * 48 + n * 8 + (lane & 3) * 2;
                float bx = be[gc], by = be[gc + 1];
                if (r0 < ne) {
                    float2 v = make_float2(c[f][n][0] + bx, c[f][n][1] + by);
                    *reinterpret_cast<float2*>(
                        g_yp + (size_t)(e * TOK + r0) * HID + gc) = v;
                }
                if (r0 + 8 < ne) {
                    float2 v = make_float2(c[f][n][2] + bx, c[f][n][3] + by);
                    *reinterpret_cast<float2*>(
                        g_yp + (size_t)(e * TOK + r0 + 8) * HID + gc) = v;
                }
            }
        }
    }
}

// ---------------- weighted combine ----------------
__global__ void combine_kernel(float* __restrict__ y) {
    int idx = blockIdx.x * blockDim.x + threadIdx.x;
    const int per_row = HID / 4;
    if (idx >= TOK * per_row) return;
    int t = idx / per_row;
    int c = (idx - t * per_row) * 4;
    float4 accv = make_float4(0.f, 0.f, 0.f, 0.f);
#pragma unroll
    for (int k = 0; k < TOPK; k++) {
        int p = g_pos[t][k];
        float wv = g_w[t][k];
        float4 v = *reinterpret_cast<const float4*>(&g_yp[(size_t)p * HID + c]);
        accv.x += wv * v.x; accv.y += wv * v.y;
        accv.z += wv * v.z; accv.w += wv * v.w;
    }
    *reinterpret_cast<float4*>(&y[(size_t)t * HID + c]) = accv;
}

// ---------------- launch ----------------
extern "C" void kernel_launch(void* const* d_in, const int* in_sizes, int n_in,
                              void* d_out, int out_size) {
    const float* x  = (const float*)d_in[0];
    const float* gw = (const float*)d_in[1];
    const float* gb = (const float*)d_in[2];
    const float* w1 = (const float*)d_in[3];
    const float* b1 = (const float*)d_in[4];
    const float* w2 = (const float*)d_in[5];
    const float* b2 = (const float*)d_in[6];
    float* y = (float*)d_out;

    cudaFuncSetAttribute(mma_gemm_kernel<true>,
                         cudaFuncAttributeMaxDynamicSharedMemorySize, SMEM_GEMM);
    cudaFuncSetAttribute(mma_gemm_kernel<false>,
                         cudaFuncAttributeMaxDynamicSharedMemorySize, SMEM_GEMM);

    init_kernel<<<1, 32>>>();
    router_kernel<<<TOK / 8, 256>>>(x, gw, gb);
    convert_x_kernel<<<(TOK * KDIM / 4 + 255) / 256, 256>>>(x);
    convert_w_kernel<0><<<(int)(((size_t)NEXP * KDIM * N1 / 4 + 255) / 256), 256>>>(w1);
    convert_w_kernel<1><<<(int)(((size_t)NEXP * KDIM * HID / 4 + 255) / 256), 256>>>(w2);

    // GEMM1 fused: n-blocks = 2880/96 = 30
    mma_gemm_kernel<true><<<dim3(16, 30, NEXP), 256, SMEM_GEMM>>>(b1);
    // GEMM2: n-blocks = 2880/192 = 15
    mma_gemm_kernel<false><<<dim3(16, 15, NEXP), 256, SMEM_GEMM>>>(b2);
    combine_kernel<<<(TOK * (HID / 4) + 255) / 256, 256>>>(y);
}